// round 10
// baseline (speedup 1.0000x reference)
#include <cuda_runtime.h>
#include <cuda_fp16.h>
#include <cstdint>

#define BB 4
#define CC 64
#define CIc 32
#define HM 128
#define HC 64
#define NTOK (HC*HC)   /* 4096 */
#define LOG2E 1.4426950408889634f

// -------- scratch (static device globals; no allocation) --------
__device__ uint32_t g_QH[BB*NTOK*16];     // 1 MB: fp16x2 words, [b][token][featpair]
__device__ uint32_t g_KHT[BB*64*16*64];   // 1 MB: [b][tile][featpair d2][token-in-tile]
__device__ __half   g_VT[BB*CIc*NTOK];    // 1 MB: [b][dim][token]
__device__ float    g_Y[BB*CC*NTOK];      // 4 MB
__device__ float    g_S1[CC], g_S2[CC];   // BN partial sums

__device__ __forceinline__ float ex2(float x){
    float r; asm("ex2.approx.f32 %0, %1;" : "=f"(r) : "f"(x));
    return r;
}

__device__ __forceinline__ uint32_t pk_f16(float lo, float hi){
    uint32_t r; asm("cvt.rn.f16x2.f32 %0, %1, %2;" : "=r"(r) : "f"(hi), "f"(lo));
    return r;
}

// non-volatile: register-only, lets ptxas pipeline LDS across MMAs.
__device__ __forceinline__ void mma_f16(float c[4], const uint32_t a[4],
                                        uint32_t b0, uint32_t b1){
    asm("mma.sync.aligned.m16n8k16.row.col.f32.f16.f16.f32 "
        "{%0,%1,%2,%3}, {%4,%5,%6,%7}, {%8,%9}, {%0,%1,%2,%3};"
        : "+f"(c[0]), "+f"(c[1]), "+f"(c[2]), "+f"(c[3])
        : "r"(a[0]), "r"(a[1]), "r"(a[2]), "r"(a[3]), "r"(b0), "r"(b1));
}

// ================= Kernel A: Q,K,V preparation (v3) =================
// grid (256, 2) x 128 threads. 2 threads per pixel (channel-parity split,
// shfl_xor merge). blockIdx.y: role 0 = Q+K from cross, role 1 = V from main.
// 2048 warps total (~14/SM) vs 512 before.
__global__ void __launch_bounds__(128) qkv_kernel(
    const float* __restrict__ mainf, const float* __restrict__ cross,
    const float* __restrict__ gw, const float* __restrict__ gb,
    const float* __restrict__ tw, const float* __restrict__ tb,
    const float* __restrict__ pw, const float* __restrict__ pb)
{
    __shared__ float swA[CC*CIc], swB[CC*CIc];
    __shared__ float sbA[CIc], sbB[CIc];
    int tid = threadIdx.x;
    int role = blockIdx.y;
    if (role == 0 && blockIdx.x == 0 && tid < CC){ g_S1[tid] = 0.f; g_S2[tid] = 0.f; }
    if (role == 0){
        for (int x = tid; x < CC*CIc; x += 128){
            int ci = x & 31, c = x >> 5;       // smem layout [c][ci]
            swA[x] = gw[ci*CC + c];
            swB[x] = tw[ci*CC + c];
        }
        if (tid < CIc){ sbA[tid] = gb[tid]; sbB[tid] = tb[tid]; }
    } else {
        for (int x = tid; x < CC*CIc; x += 128){
            int ci = x & 31, c = x >> 5;
            swA[x] = pw[ci*CC + c];
        }
        if (tid < CIc) sbA[tid] = pb[tid];
    }
    __syncthreads();

    int g = blockIdx.x*128 + tid;          // 0..32767
    int pixel = g >> 1, half = g & 1;      // 2 threads/pixel, channel parity
    int b = pixel >> 12, n = pixel & 4095;

    if (role == 0){
        // ---- Q and K (one read of cross, parity-split channels) ----
        const float* cr = cross + (b*CC)*NTOK + n;
        float aq[CIc], ak[CIc];
        #pragma unroll
        for (int i=0;i<CIc;i++){
            aq[i] = half ? 0.f : sbA[i];
            ak[i] = half ? 0.f : sbB[i];
        }
        #pragma unroll 1
        for (int c8=0; c8<4; c8++){        // 4 batches x 8 channels (this parity)
            float xc[8];
            #pragma unroll
            for (int j=0;j<8;j++) xc[j] = cr[(c8*16 + 2*j + half)*NTOK];
            #pragma unroll
            for (int j=0;j<8;j++){
                int c = c8*16 + 2*j + half;
                const float4* wq4 = (const float4*)&swA[c*CIc];
                const float4* wk4 = (const float4*)&swB[c*CIc];
                #pragma unroll
                for (int i=0;i<CIc/4;i++){
                    float4 wq = wq4[i], wk = wk4[i];
                    aq[4*i+0] += wq.x*xc[j]; aq[4*i+1] += wq.y*xc[j];
                    aq[4*i+2] += wq.z*xc[j]; aq[4*i+3] += wq.w*xc[j];
                    ak[4*i+0] += wk.x*xc[j]; ak[4*i+1] += wk.y*xc[j];
                    ak[4*i+2] += wk.z*xc[j]; ak[4*i+3] += wk.w*xc[j];
                }
            }
        }
        // merge the two parity halves (partner = adjacent lane)
        #pragma unroll
        for (int i=0;i<CIc;i++){
            aq[i] += __shfl_xor_sync(0xffffffffu, aq[i], 1);
            ak[i] += __shfl_xor_sync(0xffffffffu, ak[i], 1);
        }
        if (half == 0){
            // Q: [token][16 featpair words], fp16, pre-scaled by log2e
            uint4* qo = (uint4*)(g_QH + pixel*16);
            #pragma unroll
            for (int w4=0; w4<4; w4++){
                uint4 v;
                v.x = pk_f16(aq[8*w4+0]*LOG2E, aq[8*w4+1]*LOG2E);
                v.y = pk_f16(aq[8*w4+2]*LOG2E, aq[8*w4+3]*LOG2E);
                v.z = pk_f16(aq[8*w4+4]*LOG2E, aq[8*w4+5]*LOG2E);
                v.w = pk_f16(aq[8*w4+6]*LOG2E, aq[8*w4+7]*LOG2E);
                qo[w4] = v;
            }
        } else {
            // K: tile-transposed [b][tile][d2][token-in-tile]
            uint32_t* ko = g_KHT + ((b*64 + (n>>6))*16)*64 + (n&63);
            #pragma unroll
            for (int d2=0; d2<16; d2++) ko[d2*64] = pk_f16(ak[2*d2], ak[2*d2+1]);
        }
    } else {
        // ---- V = phi(avgpool2x2(main)), parity-split channels ----
        float av[CIc];
        #pragma unroll
        for (int i=0;i<CIc;i++) av[i] = half ? 0.f : sbA[i];
        int i2 = (n>>6)<<1, j2 = (n&63)<<1;
        const float* mb = mainf + (b*CC)*HM*HM + i2*HM + j2;
        #pragma unroll 1
        for (int c4=0; c4<8; c4++){        // 8 batches x 4 channels (this parity)
            float2 t0[4], t1[4];
            #pragma unroll
            for (int j=0;j<4;j++){
                int c = c4*8 + 2*j + half;
                t0[j] = *(const float2*)&mb[c*HM*HM];
                t1[j] = *(const float2*)&mb[c*HM*HM + HM];
            }
            #pragma unroll
            for (int j=0;j<4;j++){
                int c = c4*8 + 2*j + half;
                float xc = 0.25f*(t0[j].x + t0[j].y + t1[j].x + t1[j].y);
                const float4* w4 = (const float4*)&swA[c*CIc];
                #pragma unroll
                for (int i=0;i<CIc/4;i++){
                    float4 w = w4[i];
                    av[4*i+0] += w.x*xc; av[4*i+1] += w.y*xc;
                    av[4*i+2] += w.z*xc; av[4*i+3] += w.w*xc;
                }
            }
        }
        #pragma unroll
        for (int i=0;i<CIc;i++)
            av[i] += __shfl_xor_sync(0xffffffffu, av[i], 1);
        __half* o = g_VT + b*CIc*NTOK + n;
        if (half == 0){
            #pragma unroll
            for (int i=0;i<16;i++) o[i*NTOK] = __float2half(av[i]);
        } else {
            #pragma unroll
            for (int i=16;i<CIc;i++) o[i*NTOK] = __float2half(av[i]);
        }
    }
}

// ================= Kernel B: flash attention v5 (all-fp16 MMA) ============
// grid (32, 4), 256 threads (8 warps x 16 rows). BM=128, BN=64, d=32.
// QK^T fp16 m16n8k16 (K pre-transposed in global); softmax without max;
// PV fp16 (S C-frag == A-frag); fused epilogue Y=W*O + BN partial sums.
#define KHSTR 72   /* sKH: [16 featpairs][64 token words]; 72>=64, 72%32==8 -> bank=8*tig+gi CF */
#define VWSTR 36   /* sVW: [32 dims][32 words=64 f16 tokens]; bank=4*gi+tig CF */
#define OSTR  36
#define WSTR  33
#define SMEMF (128*OSTR + CC*WSTR + CC)   /* epilogue max user: 6784 floats; tiles need 4608 */
__global__ void __launch_bounds__(256) flash_kernel(
    const float* __restrict__ ww, const float* __restrict__ wb)
{
    __shared__ float smem_f[SMEMF];

    int b = blockIdx.y, rb = blockIdx.x;
    int tid = threadIdx.x;
    int lane = tid & 31;
    int gi = lane >> 2, tig = lane & 3;
    int warp = tid >> 5;

    const uint32_t* Qw  = g_QH + b*NTOK*16;
    const uint32_t* Kht = g_KHT + (b*64)*16*64;
    const __half*   Vbt = g_VT + b*CIc*NTOK;

    uint32_t* sKH0 = (uint32_t*)smem_f;            // 2 x 16*KHSTR words
    uint32_t* sVW0 = sKH0 + 2*16*KHSTR;            // 2 x 32*VWSTR words

    int r0 = rb*128 + warp*16 + gi;      // rows r0 and r0+8

    // Q fragments: fp16 pairs, log2e-scaled
    uint32_t qf[2][4];
    #pragma unroll
    for (int kt=0; kt<2; kt++){
        qf[kt][0] = Qw[(r0  )*16 + 8*kt + tig    ];
        qf[kt][1] = Qw[(r0+8)*16 + 8*kt + tig    ];
        qf[kt][2] = Qw[(r0  )*16 + 8*kt + tig + 4];
        qf[kt][3] = Qw[(r0+8)*16 + 8*kt + tig + 4];
    }

    float o[4][4];
    #pragma unroll
    for (int nt=0;nt<4;nt++){ o[nt][0]=0.f;o[nt][1]=0.f;o[nt][2]=0.f;o[nt][3]=0.f; }
    float l0=0.f, l1=0.f;

    // tile-load index patterns (one uint4 per thread for each of K and V)
    int krow = tid >> 4, kwg = tid & 15;   // K: featpair row, word group
    int vd = tid >> 3,   vt = tid & 7;     // V: dim, token-octet

    // ---- prologue: tile 0 into buffer 0 ----
    {
        uint4 kf = *(const uint4*)(Kht + krow*64 + kwg*4);
        uint4 vf = *(const uint4*)(Vbt + vd*NTOK + vt*8);
        *(uint4*)&sKH0[krow*KHSTR + kwg*4] = kf;
        *(uint4*)&sVW0[vd*VWSTR + vt*4] = vf;
    }

    for (int it=0; it<NTOK/64; it++){
        int buf = it & 1;
        uint4 kf, vf;
        if (it < NTOK/64 - 1){
            int tn = it + 1;
            kf = *(const uint4*)(Kht + (tn*16 + krow)*64 + kwg*4);
            vf = *(const uint4*)(Vbt + vd*NTOK + tn*64 + vt*8);
        }
        __syncthreads();

        const uint32_t* kh = sKH0 + buf*(16*KHSTR);
        const uint32_t* vW = sVW0 + buf*(32*VWSTR);

        // ---- S = Q K^T (16 x 64 per warp), fp16 MMA, log2 units ----
        float s[8][4];
        #pragma unroll
        for (int nt=0;nt<8;nt++){ s[nt][0]=0.f;s[nt][1]=0.f;s[nt][2]=0.f;s[nt][3]=0.f; }
        #pragma unroll
        for (int kt=0; kt<2; kt++){
            #pragma unroll
            for (int nt=0; nt<8; nt++){
                uint32_t b0 = kh[(8*kt + tig    )*KHSTR + nt*8 + gi];
                uint32_t b1 = kh[(8*kt + tig + 4)*KHSTR + nt*8 + gi];
                mma_f16(s[nt], qf[kt], b0, b1);
            }
        }

        // ---- softmax numerator (no max subtraction; logits bounded) ----
        #pragma unroll
        for (int nt=0;nt<8;nt++){
            float p0 = ex2(s[nt][0]), p1 = ex2(s[nt][1]);
            float p2 = ex2(s[nt][2]), p3 = ex2(s[nt][3]);
            l0 += p0 + p1; l1 += p2 + p3;
            s[nt][0]=p0; s[nt][1]=p1; s[nt][2]=p2; s[nt][3]=p3;
        }

        // ---- O += P V : fp16 MMA; S C-frag == PV A-frag ----
        #pragma unroll
        for (int kt=0; kt<4; kt++){
            uint32_t a[4];
            a[0] = pk_f16(s[2*kt  ][0], s[2*kt  ][1]);
            a[1] = pk_f16(s[2*kt  ][2], s[2*kt  ][3]);
            a[2] = pk_f16(s[2*kt+1][0], s[2*kt+1][1]);
            a[3] = pk_f16(s[2*kt+1][2], s[2*kt+1][3]);
            #pragma unroll
            for (int nt=0; nt<4; nt++){
                uint32_t b0 = vW[(nt*8+gi)*VWSTR + kt*8 + tig    ];
                uint32_t b1 = vW[(nt*8+gi)*VWSTR + kt*8 + tig + 4];
                mma_f16(o[nt], a, b0, b1);
            }
        }

        // ---- store prefetched tile into the other buffer ----
        if (it < NTOK/64 - 1){
            *(uint4*)&sKH0[(buf^1)*(16*KHSTR) + krow*KHSTR + kwg*4] = kf;
            *(uint4*)&sVW0[(buf^1)*(32*VWSTR) + vd*VWSTR + vt*4] = vf;
        }
    }

    // ---- finalize softmax denominators ----
    l0 += __shfl_xor_sync(0xffffffffu, l0, 1);
    l0 += __shfl_xor_sync(0xffffffffu, l0, 2);
    l1 += __shfl_xor_sync(0xffffffffu, l1, 1);
    l1 += __shfl_xor_sync(0xffffffffu, l1, 2);
    float inv0 = 1.f/l0, inv1 = 1.f/l1;

    // ================= fused epilogue: Y = W*O + b, BN partial sums =======
    __syncthreads();   // tiles no longer needed; repurpose smem
    float* sO  = smem_f;                 // [128][OSTR]
    float* sW  = smem_f + 128*OSTR;      // [64][WSTR]
    float* sbb = sW + CC*WSTR;           // [64]

    {   // store normalized O tile (block-local rows)
        int row0 = warp*16 + gi;
        #pragma unroll
        for (int nt=0; nt<4; nt++){
            sO[(row0  )*OSTR + nt*8 + 2*tig    ] = o[nt][0]*inv0;
            sO[(row0  )*OSTR + nt*8 + 2*tig + 1] = o[nt][1]*inv0;
            sO[(row0+8)*OSTR + nt*8 + 2*tig    ] = o[nt][2]*inv1;
            sO[(row0+8)*OSTR + nt*8 + 2*tig + 1] = o[nt][3]*inv1;
        }
    }
    for (int x = tid; x < CC*CIc; x += 256){
        int co = x >> 5, ci = x & 31;
        sW[co*WSTR + ci] = ww[x];
    }
    if (tid < CC) sbb[tid] = wb[tid];
    __syncthreads();

    int co = tid >> 2, grp = tid & 3;
    float wreg[CIc];
    #pragma unroll
    for (int ci=0; ci<CIc; ci++) wreg[ci] = sW[co*WSTR + ci];
    float bias = sbb[co];

    float s1 = 0.f, s2 = 0.f;
    float* yp = g_Y + (b*CC + co)*NTOK + rb*128;
    #pragma unroll 4
    for (int i=0; i<32; i++){
        int n = 4*i + grp;
        const float4* o4 = (const float4*)&sO[n*OSTR];
        float y = bias;
        #pragma unroll
        for (int c4=0; c4<CIc/4; c4++){
            float4 ov = o4[c4];
            y += wreg[4*c4]*ov.x + wreg[4*c4+1]*ov.y
               + wreg[4*c4+2]*ov.z + wreg[4*c4+3]*ov.w;
        }
        yp[n] = y;
        s1 += y; s2 += y*y;
    }
    s1 += __shfl_xor_sync(0xffffffffu, s1, 1);
    s1 += __shfl_xor_sync(0xffffffffu, s1, 2);
    s2 += __shfl_xor_sync(0xffffffffu, s2, 1);
    s2 += __shfl_xor_sync(0xffffffffu, s2, 2);
    if (grp == 0){
        atomicAdd(&g_S1[co], s1);
        atomicAdd(&g_S2[co], s2);
    }
}

// ================= Kernel E: BN affine + bilinear 64->128 + residual ======
// 2 horizontal output pixels per thread (shared y source columns).
__global__ void __launch_bounds__(256) final_kernel(
    const float* __restrict__ gamma, const float* __restrict__ beta,
    const float* __restrict__ mainf, float* __restrict__ out)
{
    int idx2 = blockIdx.x*256 + threadIdx.x;  // [b][co][i 0..127][m 0..63]
    int m  = idx2 & 63;
    int i  = (idx2 >> 6) & 127;
    int co = (idx2 >> 13) & 63;
    int b  = idx2 >> 19;

    float si = 0.5f*i - 0.25f;
    si = fminf(fmaxf(si, 0.f), 63.f);
    int i0 = (int)si; float wi = si - (float)i0; int i1 = min(i0+1, 63);

    int cm1 = max(m-1, 0), cp1 = min(m+1, 63);
    const float* yp  = g_Y + (b*CC + co)*NTOK;
    const float* r0p = yp + (i0 << 6);
    const float* r1p = yp + (i1 << 6);
    float wi0 = 1.f - wi;
    float ya = r0p[cm1]*wi0 + r1p[cm1]*wi;
    float yb = r0p[m  ]*wi0 + r1p[m  ]*wi;
    float yc = r0p[cp1]*wi0 + r1p[cp1]*wi;
    float ve = 0.25f*ya + 0.75f*yb;    // j = 2m   (m==0 clamps: ya==yb)
    float vo = 0.75f*yb + 0.25f*yc;    // j = 2m+1 (m==63 clamps: yc==yb)

    const float invN = 1.f/(BB*NTOK);
    float mean = g_S1[co]*invN;
    float var  = g_S2[co]*invN - mean*mean;
    float rstd = rsqrtf(var + 1e-5f);
    float gsc = rstd*gamma[co];
    float bsc = beta[co] - mean*gsc;

    int base = ((b*CC + co)*HM + i)*HM + 2*m;
    float2 mo = *(const float2*)&mainf[base];
    float2 res;
    res.x = ve*gsc + bsc + mo.x;
    res.y = vo*gsc + bsc + mo.y;
    *(float2*)&out[base] = res;
}

// ======================= launch =======================
extern "C" void kernel_launch(void* const* d_in, const int* in_sizes, int n_in,
                              void* d_out, int out_size)
{
    const float* mainf = (const float*)d_in[0];
    const float* cross = (const float*)d_in[1];
    const float* gw    = (const float*)d_in[2];
    const float* gb    = (const float*)d_in[3];
    const float* tw    = (const float*)d_in[4];
    const float* tb    = (const float*)d_in[5];
    const float* pw    = (const float*)d_in[6];
    const float* pb    = (const float*)d_in[7];
    const float* ww    = (const float*)d_in[8];
    const float* wb    = (const float*)d_in[9];
    const float* gamma = (const float*)d_in[10];
    const float* beta  = (const float*)d_in[11];
    float* out = (float*)d_out;

    qkv_kernel<<<dim3((2*BB*NTOK)/128, 2), 128>>>(mainf, cross, gw, gb, tw, tb, pw, pb);
    flash_kernel<<<dim3(NTOK/128, BB), 256>>>(ww, wb);
    final_kernel<<<(BB*CC*HM*64)/256, 256>>>(gamma, beta, mainf, out);
}

// round 11
// speedup vs baseline: 1.1713x; 1.1713x over previous
#include <cuda_runtime.h>
#include <cuda_fp16.h>
#include <cstdint>

#define BB 4
#define CC 64
#define CIc 32
#define HM 128
#define HC 64
#define NTOK (HC*HC)   /* 4096 */
#define LOG2E 1.4426950408889634f

// -------- scratch (static device globals; no allocation) --------
__device__ uint32_t g_QH[BB*NTOK*16];     // 1 MB: fp16x2 words, [b][token][featpair]
__device__ uint32_t g_KHT[BB*64*16*64];   // 1 MB: [b][tile][featpair d2][token-in-tile]
__device__ __half   g_VT[BB*CIc*NTOK];    // 1 MB: [b][dim][token]
__device__ float    g_Y[BB*CC*NTOK];      // 4 MB
__device__ float    g_S1[CC], g_S2[CC];   // BN partial sums

__device__ __forceinline__ float ex2(float x){
    float r; asm("ex2.approx.f32 %0, %1;" : "=f"(r) : "f"(x));
    return r;
}

__device__ __forceinline__ uint32_t pk_f16(float lo, float hi){
    uint32_t r; asm("cvt.rn.f16x2.f32 %0, %1, %2;" : "=r"(r) : "f"(hi), "f"(lo));
    return r;
}

// non-volatile: register-only, lets ptxas pipeline LDS across MMAs.
__device__ __forceinline__ void mma_f16(float c[4], const uint32_t a[4],
                                        uint32_t b0, uint32_t b1){
    asm("mma.sync.aligned.m16n8k16.row.col.f32.f16.f16.f32 "
        "{%0,%1,%2,%3}, {%4,%5,%6,%7}, {%8,%9}, {%0,%1,%2,%3};"
        : "+f"(c[0]), "+f"(c[1]), "+f"(c[2]), "+f"(c[3])
        : "r"(a[0]), "r"(a[1]), "r"(a[2]), "r"(a[3]), "r"(b0), "r"(b1));
}

// ================= Kernel A: Q,K,V preparation (v4) =================
// grid (128, 2) x 128 threads. One thread per pixel (as in the proven R9
// kernel — identical per-thread load patterns), but the two passes are split
// across blockIdx.y roles: role 0 = Q+K from cross, role 1 = V from main.
// They read disjoint inputs and overlap across SMs (1024 warps total).
__global__ void __launch_bounds__(128) qkv_kernel(
    const float* __restrict__ mainf, const float* __restrict__ cross,
    const float* __restrict__ gw, const float* __restrict__ gb,
    const float* __restrict__ tw, const float* __restrict__ tb,
    const float* __restrict__ pw, const float* __restrict__ pb)
{
    __shared__ float swA[CC*CIc], swB[CC*CIc];
    __shared__ float sbA[CIc], sbB[CIc];
    int tid = threadIdx.x;
    int role = blockIdx.y;
    if (role == 0 && blockIdx.x == 0 && tid < CC){ g_S1[tid] = 0.f; g_S2[tid] = 0.f; }
    if (role == 0){
        for (int x = tid; x < CC*CIc; x += 128){
            int ci = x & 31, c = x >> 5;       // smem layout [c][ci]
            swA[x] = gw[ci*CC + c];
            swB[x] = tw[ci*CC + c];
        }
        if (tid < CIc){ sbA[tid] = gb[tid]; sbB[tid] = tb[tid]; }
    } else {
        for (int x = tid; x < CC*CIc; x += 128){
            int ci = x & 31, c = x >> 5;
            swA[x] = pw[ci*CC + c];
        }
        if (tid < CIc) sbA[tid] = pb[tid];
    }
    __syncthreads();

    int idx = blockIdx.x*128 + tid;        // 0..16383 (one pixel per thread)
    int b = idx >> 12, n = idx & 4095;

    if (role == 0){
        // ---- Q and K together (one read of cross; 8-ch load batches) ----
        const float* cr = cross + (b*CC)*NTOK + n;
        float aq[CIc], ak[CIc];
        #pragma unroll
        for (int i=0;i<CIc;i++){ aq[i] = sbA[i]; ak[i] = sbB[i]; }
        #pragma unroll 1
        for (int c8=0; c8<8; c8++){
            float xc[8];
            #pragma unroll
            for (int j=0;j<8;j++) xc[j] = cr[(c8*8 + j)*NTOK];
            #pragma unroll
            for (int j=0;j<8;j++){
                int c = c8*8 + j;
                const float4* wq4 = (const float4*)&swA[c*CIc];
                const float4* wk4 = (const float4*)&swB[c*CIc];
                #pragma unroll
                for (int i=0;i<CIc/4;i++){
                    float4 wq = wq4[i], wk = wk4[i];
                    aq[4*i+0] += wq.x*xc[j]; aq[4*i+1] += wq.y*xc[j];
                    aq[4*i+2] += wq.z*xc[j]; aq[4*i+3] += wq.w*xc[j];
                    ak[4*i+0] += wk.x*xc[j]; ak[4*i+1] += wk.y*xc[j];
                    ak[4*i+2] += wk.z*xc[j]; ak[4*i+3] += wk.w*xc[j];
                }
            }
        }
        // Q: [token][16 featpair words], fp16, pre-scaled by log2e
        uint4* qo = (uint4*)(g_QH + idx*16);
        #pragma unroll
        for (int w4=0; w4<4; w4++){
            uint4 v;
            v.x = pk_f16(aq[8*w4+0]*LOG2E, aq[8*w4+1]*LOG2E);
            v.y = pk_f16(aq[8*w4+2]*LOG2E, aq[8*w4+3]*LOG2E);
            v.z = pk_f16(aq[8*w4+4]*LOG2E, aq[8*w4+5]*LOG2E);
            v.w = pk_f16(aq[8*w4+6]*LOG2E, aq[8*w4+7]*LOG2E);
            qo[w4] = v;
        }
        // K: tile-transposed [b][tile][d2][token-in-tile]
        uint32_t* ko = g_KHT + ((b*64 + (n>>6))*16)*64 + (n&63);
        #pragma unroll
        for (int d2=0; d2<16; d2++) ko[d2*64] = pk_f16(ak[2*d2], ak[2*d2+1]);
    } else {
        // ---- V = phi(avgpool2x2(main)), fp16 transposed ----
        float av[CIc];
        #pragma unroll
        for (int i=0;i<CIc;i++) av[i] = sbA[i];
        int i2 = (n>>6)<<1, j2 = (n&63)<<1;
        const float* mb = mainf + (b*CC)*HM*HM + i2*HM + j2;
        #pragma unroll 1
        for (int c4=0; c4<16; c4++){
            float2 t0[4], t1[4];
            #pragma unroll
            for (int j=0;j<4;j++){
                int c = c4*4 + j;
                t0[j] = *(const float2*)&mb[c*HM*HM];
                t1[j] = *(const float2*)&mb[c*HM*HM + HM];
            }
            #pragma unroll
            for (int j=0;j<4;j++){
                int c = c4*4 + j;
                float xc = 0.25f*(t0[j].x + t0[j].y + t1[j].x + t1[j].y);
                const float4* w4 = (const float4*)&swA[c*CIc];
                #pragma unroll
                for (int i=0;i<CIc/4;i++){
                    float4 w = w4[i];
                    av[4*i+0] += w.x*xc; av[4*i+1] += w.y*xc;
                    av[4*i+2] += w.z*xc; av[4*i+3] += w.w*xc;
                }
            }
        }
        __half* o = g_VT + b*CIc*NTOK + n;
        #pragma unroll
        for (int i=0;i<CIc;i++) o[i*NTOK] = __float2half(av[i]);
    }
}

// ================= Kernel B: flash attention v5 (all-fp16 MMA) ============
// grid (32, 4), 256 threads (8 warps x 16 rows). BM=128, BN=64, d=32.
// QK^T fp16 m16n8k16 (K pre-transposed in global); softmax without max;
// PV fp16 (S C-frag == A-frag); fused epilogue Y=W*O + BN partial sums.
#define KHSTR 72   /* sKH: [16 featpairs][64 token words]; 72>=64, 72%32==8 -> bank=8*tig+gi CF */
#define VWSTR 36   /* sVW: [32 dims][32 words=64 f16 tokens]; bank=4*gi+tig CF */
#define OSTR  36
#define WSTR  33
#define SMEMF (128*OSTR + CC*WSTR + CC)   /* epilogue max user: 6784 floats; tiles need 4608 */
__global__ void __launch_bounds__(256) flash_kernel(
    const float* __restrict__ ww, const float* __restrict__ wb)
{
    __shared__ float smem_f[SMEMF];

    int b = blockIdx.y, rb = blockIdx.x;
    int tid = threadIdx.x;
    int lane = tid & 31;
    int gi = lane >> 2, tig = lane & 3;
    int warp = tid >> 5;

    const uint32_t* Qw  = g_QH + b*NTOK*16;
    const uint32_t* Kht = g_KHT + (b*64)*16*64;
    const __half*   Vbt = g_VT + b*CIc*NTOK;

    uint32_t* sKH0 = (uint32_t*)smem_f;            // 2 x 16*KHSTR words
    uint32_t* sVW0 = sKH0 + 2*16*KHSTR;            // 2 x 32*VWSTR words

    int r0 = rb*128 + warp*16 + gi;      // rows r0 and r0+8

    // Q fragments: fp16 pairs, log2e-scaled
    uint32_t qf[2][4];
    #pragma unroll
    for (int kt=0; kt<2; kt++){
        qf[kt][0] = Qw[(r0  )*16 + 8*kt + tig    ];
        qf[kt][1] = Qw[(r0+8)*16 + 8*kt + tig    ];
        qf[kt][2] = Qw[(r0  )*16 + 8*kt + tig + 4];
        qf[kt][3] = Qw[(r0+8)*16 + 8*kt + tig + 4];
    }

    float o[4][4];
    #pragma unroll
    for (int nt=0;nt<4;nt++){ o[nt][0]=0.f;o[nt][1]=0.f;o[nt][2]=0.f;o[nt][3]=0.f; }
    float l0=0.f, l1=0.f;

    // tile-load index patterns (one uint4 per thread for each of K and V)
    int krow = tid >> 4, kwg = tid & 15;   // K: featpair row, word group
    int vd = tid >> 3,   vt = tid & 7;     // V: dim, token-octet

    // ---- prologue: tile 0 into buffer 0 ----
    {
        uint4 kf = *(const uint4*)(Kht + krow*64 + kwg*4);
        uint4 vf = *(const uint4*)(Vbt + vd*NTOK + vt*8);
        *(uint4*)&sKH0[krow*KHSTR + kwg*4] = kf;
        *(uint4*)&sVW0[vd*VWSTR + vt*4] = vf;
    }

    for (int it=0; it<NTOK/64; it++){
        int buf = it & 1;
        uint4 kf, vf;
        if (it < NTOK/64 - 1){
            int tn = it + 1;
            kf = *(const uint4*)(Kht + (tn*16 + krow)*64 + kwg*4);
            vf = *(const uint4*)(Vbt + vd*NTOK + tn*64 + vt*8);
        }
        __syncthreads();

        const uint32_t* kh = sKH0 + buf*(16*KHSTR);
        const uint32_t* vW = sVW0 + buf*(32*VWSTR);

        // ---- S = Q K^T (16 x 64 per warp), fp16 MMA, log2 units ----
        float s[8][4];
        #pragma unroll
        for (int nt=0;nt<8;nt++){ s[nt][0]=0.f;s[nt][1]=0.f;s[nt][2]=0.f;s[nt][3]=0.f; }
        #pragma unroll
        for (int kt=0; kt<2; kt++){
            #pragma unroll
            for (int nt=0; nt<8; nt++){
                uint32_t b0 = kh[(8*kt + tig    )*KHSTR + nt*8 + gi];
                uint32_t b1 = kh[(8*kt + tig + 4)*KHSTR + nt*8 + gi];
                mma_f16(s[nt], qf[kt], b0, b1);
            }
        }

        // ---- softmax numerator (no max subtraction; logits bounded) ----
        #pragma unroll
        for (int nt=0;nt<8;nt++){
            float p0 = ex2(s[nt][0]), p1 = ex2(s[nt][1]);
            float p2 = ex2(s[nt][2]), p3 = ex2(s[nt][3]);
            l0 += p0 + p1; l1 += p2 + p3;
            s[nt][0]=p0; s[nt][1]=p1; s[nt][2]=p2; s[nt][3]=p3;
        }

        // ---- O += P V : fp16 MMA; S C-frag == PV A-frag ----
        #pragma unroll
        for (int kt=0; kt<4; kt++){
            uint32_t a[4];
            a[0] = pk_f16(s[2*kt  ][0], s[2*kt  ][1]);
            a[1] = pk_f16(s[2*kt  ][2], s[2*kt  ][3]);
            a[2] = pk_f16(s[2*kt+1][0], s[2*kt+1][1]);
            a[3] = pk_f16(s[2*kt+1][2], s[2*kt+1][3]);
            #pragma unroll
            for (int nt=0; nt<4; nt++){
                uint32_t b0 = vW[(nt*8+gi)*VWSTR + kt*8 + tig    ];
                uint32_t b1 = vW[(nt*8+gi)*VWSTR + kt*8 + tig + 4];
                mma_f16(o[nt], a, b0, b1);
            }
        }

        // ---- store prefetched tile into the other buffer ----
        if (it < NTOK/64 - 1){
            *(uint4*)&sKH0[(buf^1)*(16*KHSTR) + krow*KHSTR + kwg*4] = kf;
            *(uint4*)&sVW0[(buf^1)*(32*VWSTR) + vd*VWSTR + vt*4] = vf;
        }
    }

    // ---- finalize softmax denominators ----
    l0 += __shfl_xor_sync(0xffffffffu, l0, 1);
    l0 += __shfl_xor_sync(0xffffffffu, l0, 2);
    l1 += __shfl_xor_sync(0xffffffffu, l1, 1);
    l1 += __shfl_xor_sync(0xffffffffu, l1, 2);
    float inv0 = 1.f/l0, inv1 = 1.f/l1;

    // ================= fused epilogue: Y = W*O + b, BN partial sums =======
    __syncthreads();   // tiles no longer needed; repurpose smem
    float* sO  = smem_f;                 // [128][OSTR]
    float* sW  = smem_f + 128*OSTR;      // [64][WSTR]
    float* sbb = sW + CC*WSTR;           // [64]

    {   // store normalized O tile (block-local rows)
        int row0 = warp*16 + gi;
        #pragma unroll
        for (int nt=0; nt<4; nt++){
            sO[(row0  )*OSTR + nt*8 + 2*tig    ] = o[nt][0]*inv0;
            sO[(row0  )*OSTR + nt*8 + 2*tig + 1] = o[nt][1]*inv0;
            sO[(row0+8)*OSTR + nt*8 + 2*tig    ] = o[nt][2]*inv1;
            sO[(row0+8)*OSTR + nt*8 + 2*tig + 1] = o[nt][3]*inv1;
        }
    }
    for (int x = tid; x < CC*CIc; x += 256){
        int co = x >> 5, ci = x & 31;
        sW[co*WSTR + ci] = ww[x];
    }
    if (tid < CC) sbb[tid] = wb[tid];
    __syncthreads();

    int co = tid >> 2, grp = tid & 3;
    float wreg[CIc];
    #pragma unroll
    for (int ci=0; ci<CIc; ci++) wreg[ci] = sW[co*WSTR + ci];
    float bias = sbb[co];

    float s1 = 0.f, s2 = 0.f;
    float* yp = g_Y + (b*CC + co)*NTOK + rb*128;
    #pragma unroll 4
    for (int i=0; i<32; i++){
        int n = 4*i + grp;
        const float4* o4 = (const float4*)&sO[n*OSTR];
        float y = bias;
        #pragma unroll
        for (int c4=0; c4<CIc/4; c4++){
            float4 ov = o4[c4];
            y += wreg[4*c4]*ov.x + wreg[4*c4+1]*ov.y
               + wreg[4*c4+2]*ov.z + wreg[4*c4+3]*ov.w;
        }
        yp[n] = y;
        s1 += y; s2 += y*y;
    }
    s1 += __shfl_xor_sync(0xffffffffu, s1, 1);
    s1 += __shfl_xor_sync(0xffffffffu, s1, 2);
    s2 += __shfl_xor_sync(0xffffffffu, s2, 1);
    s2 += __shfl_xor_sync(0xffffffffu, s2, 2);
    if (grp == 0){
        atomicAdd(&g_S1[co], s1);
        atomicAdd(&g_S2[co], s2);
    }
}

// ================= Kernel E: BN affine + bilinear 64->128 + residual ======
// 2 horizontal output pixels per thread (shared y source columns).
__global__ void __launch_bounds__(256) final_kernel(
    const float* __restrict__ gamma, const float* __restrict__ beta,
    const float* __restrict__ mainf, float* __restrict__ out)
{
    int idx2 = blockIdx.x*256 + threadIdx.x;  // [b][co][i 0..127][m 0..63]
    int m  = idx2 & 63;
    int i  = (idx2 >> 6) & 127;
    int co = (idx2 >> 13) & 63;
    int b  = idx2 >> 19;

    float si = 0.5f*i - 0.25f;
    si = fminf(fmaxf(si, 0.f), 63.f);
    int i0 = (int)si; float wi = si - (float)i0; int i1 = min(i0+1, 63);

    int cm1 = max(m-1, 0), cp1 = min(m+1, 63);
    const float* yp  = g_Y + (b*CC + co)*NTOK;
    const float* r0p = yp + (i0 << 6);
    const float* r1p = yp + (i1 << 6);
    float wi0 = 1.f - wi;
    float ya = r0p[cm1]*wi0 + r1p[cm1]*wi;
    float yb = r0p[m  ]*wi0 + r1p[m  ]*wi;
    float yc = r0p[cp1]*wi0 + r1p[cp1]*wi;
    float ve = 0.25f*ya + 0.75f*yb;    // j = 2m   (m==0 clamps: ya==yb)
    float vo = 0.75f*yb + 0.25f*yc;    // j = 2m+1 (m==63 clamps: yc==yb)

    const float invN = 1.f/(BB*NTOK);
    float mean = g_S1[co]*invN;
    float var  = g_S2[co]*invN - mean*mean;
    float rstd = rsqrtf(var + 1e-5f);
    float gsc = rstd*gamma[co];
    float bsc = beta[co] - mean*gsc;

    int base = ((b*CC + co)*HM + i)*HM + 2*m;
    float2 mo = *(const float2*)&mainf[base];
    float2 res;
    res.x = ve*gsc + bsc + mo.x;
    res.y = vo*gsc + bsc + mo.y;
    *(float2*)&out[base] = res;
}

// ======================= launch =======================
extern "C" void kernel_launch(void* const* d_in, const int* in_sizes, int n_in,
                              void* d_out, int out_size)
{
    const float* mainf = (const float*)d_in[0];
    const float* cross = (const float*)d_in[1];
    const float* gw    = (const float*)d_in[2];
    const float* gb    = (const float*)d_in[3];
    const float* tw    = (const float*)d_in[4];
    const float* tb    = (const float*)d_in[5];
    const float* pw    = (const float*)d_in[6];
    const float* pb    = (const float*)d_in[7];
    const float* ww    = (const float*)d_in[8];
    const float* wb    = (const float*)d_in[9];
    const float* gamma = (const float*)d_in[10];
    const float* beta  = (const float*)d_in[11];
    float* out = (float*)d_out;

    qkv_kernel<<<dim3((BB*NTOK)/128, 2), 128>>>(mainf, cross, gw, gb, tw, tb, pw, pb);
    flash_kernel<<<dim3(NTOK/128, BB), 256>>>(ww, wb);
    final_kernel<<<(BB*CC*HM*64)/256, 256>>>(gamma, beta, mainf, out);
}

// round 12
// speedup vs baseline: 1.4053x; 1.1998x over previous
#include <cuda_runtime.h>
#include <cuda_fp16.h>
#include <cstdint>

#define BB 4
#define CC 64
#define CIc 32
#define HM 128
#define HC 64
#define NTOK (HC*HC)   /* 4096 */
#define LOG2E 1.4426950408889634f

// -------- scratch (static device globals; no allocation) --------
__device__ uint32_t g_QH[BB*NTOK*16];     // 1 MB: fp16x2 words, [b][token][featpair]
__device__ uint32_t g_KHT[BB*64*16*64];   // 1 MB: [b][tile][featpair d2][token-in-tile]
__device__ __half   g_VT[BB*CIc*NTOK];    // 1 MB: [b][dim][token]
__device__ float    g_Y[BB*CC*NTOK];      // 4 MB
__device__ float    g_S1[CC], g_S2[CC];   // BN partial sums

__device__ __forceinline__ float ex2(float x){
    float r; asm("ex2.approx.f32 %0, %1;" : "=f"(r) : "f"(x));
    return r;
}

__device__ __forceinline__ uint32_t pk_f16(float lo, float hi){
    uint32_t r; asm("cvt.rn.f16x2.f32 %0, %1, %2;" : "=r"(r) : "f"(hi), "f"(lo));
    return r;
}

// non-volatile: register-only, lets ptxas pipeline LDS across MMAs.
__device__ __forceinline__ void mma_f16(float c[4], const uint32_t a[4],
                                        uint32_t b0, uint32_t b1){
    asm("mma.sync.aligned.m16n8k16.row.col.f32.f16.f16.f32 "
        "{%0,%1,%2,%3}, {%4,%5,%6,%7}, {%8,%9}, {%0,%1,%2,%3};"
        : "+f"(c[0]), "+f"(c[1]), "+f"(c[2]), "+f"(c[3])
        : "r"(a[0]), "r"(a[1]), "r"(a[2]), "r"(a[3]), "r"(b0), "r"(b1));
}

// ================= Kernel A: Q,K,V preparation (R9-proven version) ========
// 128 CTAs x 128 threads. Pass 1: merged Q+K over cross (8-ch load batches).
// Pass 2: V = phi(avgpool2x2(main)) with 4-ch float2 batches.
__global__ void __launch_bounds__(128) qkv_kernel(
    const float* __restrict__ mainf, const float* __restrict__ cross,
    const float* __restrict__ gw, const float* __restrict__ gb,
    const float* __restrict__ tw, const float* __restrict__ tb,
    const float* __restrict__ pw, const float* __restrict__ pb)
{
    __shared__ float swq[CC*CIc], swk[CC*CIc], swv[CC*CIc];
    __shared__ float sbq[CIc], sbk[CIc], sbv[CIc];
    int tid = threadIdx.x;
    if (blockIdx.x == 0 && tid < CC){ g_S1[tid] = 0.f; g_S2[tid] = 0.f; }
    for (int x = tid; x < CC*CIc; x += 128){
        int ci = x & 31, c = x >> 5;       // smem layout [c][ci]
        swq[x] = gw[ci*CC + c];
        swk[x] = tw[ci*CC + c];
        swv[x] = pw[ci*CC + c];
    }
    if (tid < CIc){ sbq[tid]=gb[tid]; sbk[tid]=tb[tid]; sbv[tid]=pb[tid]; }
    __syncthreads();

    int idx = blockIdx.x*128 + tid;        // 0..16383
    int b = idx >> 12, n = idx & 4095;
    const float* cr = cross + (b*CC)*NTOK + n;

    // ---- pass 1: Q and K together (one read of cross) ----
    float aq[CIc], ak[CIc];
    #pragma unroll
    for (int i=0;i<CIc;i++){ aq[i] = sbq[i]; ak[i] = sbk[i]; }
    #pragma unroll 1
    for (int c8=0; c8<8; c8++){
        float xc[8];
        #pragma unroll
        for (int j=0;j<8;j++) xc[j] = cr[(c8*8 + j)*NTOK];
        #pragma unroll
        for (int j=0;j<8;j++){
            int c = c8*8 + j;
            const float4* wq4 = (const float4*)&swq[c*CIc];
            const float4* wk4 = (const float4*)&swk[c*CIc];
            #pragma unroll
            for (int i=0;i<CIc/4;i++){
                float4 wq = wq4[i], wk = wk4[i];
                aq[4*i+0] += wq.x*xc[j]; aq[4*i+1] += wq.y*xc[j];
                aq[4*i+2] += wq.z*xc[j]; aq[4*i+3] += wq.w*xc[j];
                ak[4*i+0] += wk.x*xc[j]; ak[4*i+1] += wk.y*xc[j];
                ak[4*i+2] += wk.z*xc[j]; ak[4*i+3] += wk.w*xc[j];
            }
        }
    }
    {   // Q: [token][16 featpair words], fp16, pre-scaled by log2e
        uint4* qo = (uint4*)(g_QH + idx*16);
        #pragma unroll
        for (int w4=0; w4<4; w4++){
            uint4 v;
            v.x = pk_f16(aq[8*w4+0]*LOG2E, aq[8*w4+1]*LOG2E);
            v.y = pk_f16(aq[8*w4+2]*LOG2E, aq[8*w4+3]*LOG2E);
            v.z = pk_f16(aq[8*w4+4]*LOG2E, aq[8*w4+5]*LOG2E);
            v.w = pk_f16(aq[8*w4+6]*LOG2E, aq[8*w4+7]*LOG2E);
            qo[w4] = v;
        }
        // K: tile-transposed [b][tile][d2][token-in-tile]
        uint32_t* ko = g_KHT + ((b*64 + (n>>6))*16)*64 + (n&63);
        #pragma unroll
        for (int d2=0; d2<16; d2++) ko[d2*64] = pk_f16(ak[2*d2], ak[2*d2+1]);
    }

    // ---- pass 2: V (avg-pool 2x2 of main, then phi), fp16 transposed ----
    float av[CIc];
    #pragma unroll
    for (int i=0;i<CIc;i++) av[i] = sbv[i];
    int i2 = (n>>6)<<1, j2 = (n&63)<<1;
    const float* mb = mainf + (b*CC)*HM*HM + i2*HM + j2;
    #pragma unroll 1
    for (int c4=0; c4<16; c4++){
        float2 t0[4], t1[4];
        #pragma unroll
        for (int j=0;j<4;j++){
            int c = c4*4 + j;
            t0[j] = *(const float2*)&mb[c*HM*HM];
            t1[j] = *(const float2*)&mb[c*HM*HM + HM];
        }
        #pragma unroll
        for (int j=0;j<4;j++){
            int c = c4*4 + j;
            float xc = 0.25f*(t0[j].x + t0[j].y + t1[j].x + t1[j].y);
            const float4* w4 = (const float4*)&swv[c*CIc];
            #pragma unroll
            for (int i=0;i<CIc/4;i++){
                float4 w = w4[i];
                av[4*i+0] += w.x*xc; av[4*i+1] += w.y*xc;
                av[4*i+2] += w.z*xc; av[4*i+3] += w.w*xc;
            }
        }
    }
    {
        __half* o = g_VT + b*CIc*NTOK + n;
        #pragma unroll
        for (int i=0;i<CIc;i++) o[i*NTOK] = __float2half(av[i]);
    }
}

// ================= Kernel B: flash attention v6 (BM=64, 2 CTAs/SM) ========
// grid (64, 4), 128 threads (4 warps x 16 rows). BM=64, BN=64, d=32.
// Same per-warp work as v5; halved CTA size co-schedules 2 CTAs/SM so
// barrier bubbles and LDS latency interleave across independent CTAs.
#define KHSTR 72   /* sKH: [16 featpairs][64 token words]; 72%32==8 -> bank=8*tig+gi CF */
#define VWSTR 36   /* sVW: [32 dims][32 words=64 f16 tokens]; bank=4*gi+tig CF */
#define OSTR  36
#define WSTR  33
#define SMEMF (2*16*KHSTR + 2*32*VWSTR)   /* 4608 floats; epilogue needs 4480 */
__global__ void __launch_bounds__(128) flash_kernel(
    const float* __restrict__ ww, const float* __restrict__ wb)
{
    __shared__ float smem_f[SMEMF];

    int b = blockIdx.y, rb = blockIdx.x;
    int tid = threadIdx.x;
    int lane = tid & 31;
    int gi = lane >> 2, tig = lane & 3;
    int warp = tid >> 5;

    const uint32_t* Qw  = g_QH + b*NTOK*16;
    const uint32_t* Kht = g_KHT + (b*64)*16*64;
    const __half*   Vbt = g_VT + b*CIc*NTOK;

    uint32_t* sKH0 = (uint32_t*)smem_f;            // 2 x 16*KHSTR words
    uint32_t* sVW0 = sKH0 + 2*16*KHSTR;            // 2 x 32*VWSTR words

    int r0 = rb*64 + warp*16 + gi;      // rows r0 and r0+8

    // Q fragments: fp16 pairs, log2e-scaled
    uint32_t qf[2][4];
    #pragma unroll
    for (int kt=0; kt<2; kt++){
        qf[kt][0] = Qw[(r0  )*16 + 8*kt + tig    ];
        qf[kt][1] = Qw[(r0+8)*16 + 8*kt + tig    ];
        qf[kt][2] = Qw[(r0  )*16 + 8*kt + tig + 4];
        qf[kt][3] = Qw[(r0+8)*16 + 8*kt + tig + 4];
    }

    float o[4][4];
    #pragma unroll
    for (int nt=0;nt<4;nt++){ o[nt][0]=0.f;o[nt][1]=0.f;o[nt][2]=0.f;o[nt][3]=0.f; }
    float l0=0.f, l1=0.f;

    // tile-load index patterns: 128 threads, each loads 2 uint4 for K and 2 for V
    int kr0 = tid >> 4,        kw0 = tid & 15;          // K uint4 #0
    int kr1 = (tid+128) >> 4,  kw1 = tid & 15;          // K uint4 #1
    int vd0 = tid >> 3,        vt0 = tid & 7;           // V uint4 #0
    int vd1 = (tid+128) >> 3,  vt1 = tid & 7;           // V uint4 #1

    // ---- prologue: tile 0 into buffer 0 ----
    {
        uint4 ka = *(const uint4*)(Kht + kr0*64 + kw0*4);
        uint4 kb = *(const uint4*)(Kht + kr1*64 + kw1*4);
        uint4 va = *(const uint4*)(Vbt + vd0*NTOK + vt0*8);
        uint4 vb = *(const uint4*)(Vbt + vd1*NTOK + vt1*8);
        *(uint4*)&sKH0[kr0*KHSTR + kw0*4] = ka;
        *(uint4*)&sKH0[kr1*KHSTR + kw1*4] = kb;
        *(uint4*)&sVW0[vd0*VWSTR + vt0*4] = va;
        *(uint4*)&sVW0[vd1*VWSTR + vt1*4] = vb;
    }

    for (int it=0; it<NTOK/64; it++){
        int buf = it & 1;
        uint4 ka, kb, va, vb;
        if (it < NTOK/64 - 1){
            int tn = it + 1;
            ka = *(const uint4*)(Kht + (tn*16 + kr0)*64 + kw0*4);
            kb = *(const uint4*)(Kht + (tn*16 + kr1)*64 + kw1*4);
            va = *(const uint4*)(Vbt + vd0*NTOK + tn*64 + vt0*8);
            vb = *(const uint4*)(Vbt + vd1*NTOK + tn*64 + vt1*8);
        }
        __syncthreads();

        const uint32_t* kh = sKH0 + buf*(16*KHSTR);
        const uint32_t* vW = sVW0 + buf*(32*VWSTR);

        // ---- S = Q K^T (16 x 64 per warp), fp16 MMA, log2 units ----
        float s[8][4];
        #pragma unroll
        for (int nt=0;nt<8;nt++){ s[nt][0]=0.f;s[nt][1]=0.f;s[nt][2]=0.f;s[nt][3]=0.f; }
        #pragma unroll
        for (int kt=0; kt<2; kt++){
            #pragma unroll
            for (int nt=0; nt<8; nt++){
                uint32_t b0 = kh[(8*kt + tig    )*KHSTR + nt*8 + gi];
                uint32_t b1 = kh[(8*kt + tig + 4)*KHSTR + nt*8 + gi];
                mma_f16(s[nt], qf[kt], b0, b1);
            }
        }

        // ---- softmax numerator (no max subtraction; logits bounded) ----
        #pragma unroll
        for (int nt=0;nt<8;nt++){
            float p0 = ex2(s[nt][0]), p1 = ex2(s[nt][1]);
            float p2 = ex2(s[nt][2]), p3 = ex2(s[nt][3]);
            l0 += p0 + p1; l1 += p2 + p3;
            s[nt][0]=p0; s[nt][1]=p1; s[nt][2]=p2; s[nt][3]=p3;
        }

        // ---- O += P V : fp16 MMA; S C-frag == PV A-frag ----
        #pragma unroll
        for (int kt=0; kt<4; kt++){
            uint32_t a[4];
            a[0] = pk_f16(s[2*kt  ][0], s[2*kt  ][1]);
            a[1] = pk_f16(s[2*kt  ][2], s[2*kt  ][3]);
            a[2] = pk_f16(s[2*kt+1][0], s[2*kt+1][1]);
            a[3] = pk_f16(s[2*kt+1][2], s[2*kt+1][3]);
            #pragma unroll
            for (int nt=0; nt<4; nt++){
                uint32_t b0 = vW[(nt*8+gi)*VWSTR + kt*8 + tig    ];
                uint32_t b1 = vW[(nt*8+gi)*VWSTR + kt*8 + tig + 4];
                mma_f16(o[nt], a, b0, b1);
            }
        }

        // ---- store prefetched tile into the other buffer ----
        if (it < NTOK/64 - 1){
            uint32_t* kn = sKH0 + (buf^1)*(16*KHSTR);
            uint32_t* vn = sVW0 + (buf^1)*(32*VWSTR);
            *(uint4*)&kn[kr0*KHSTR + kw0*4] = ka;
            *(uint4*)&kn[kr1*KHSTR + kw1*4] = kb;
            *(uint4*)&vn[vd0*VWSTR + vt0*4] = va;
            *(uint4*)&vn[vd1*VWSTR + vt1*4] = vb;
        }
    }

    // ---- finalize softmax denominators ----
    l0 += __shfl_xor_sync(0xffffffffu, l0, 1);
    l0 += __shfl_xor_sync(0xffffffffu, l0, 2);
    l1 += __shfl_xor_sync(0xffffffffu, l1, 1);
    l1 += __shfl_xor_sync(0xffffffffu, l1, 2);
    float inv0 = 1.f/l0, inv1 = 1.f/l1;

    // ================= fused epilogue: Y = W*O + b, BN partial sums =======
    __syncthreads();   // tiles no longer needed; repurpose smem
    float* sO  = smem_f;                 // [64][OSTR]
    float* sW  = smem_f + 64*OSTR;       // [64][WSTR]
    float* sbb = sW + CC*WSTR;           // [64]

    {   // store normalized O tile (block-local rows 0..63)
        int row0 = warp*16 + gi;
        #pragma unroll
        for (int nt=0; nt<4; nt++){
            sO[(row0  )*OSTR + nt*8 + 2*tig    ] = o[nt][0]*inv0;
            sO[(row0  )*OSTR + nt*8 + 2*tig + 1] = o[nt][1]*inv0;
            sO[(row0+8)*OSTR + nt*8 + 2*tig    ] = o[nt][2]*inv1;
            sO[(row0+8)*OSTR + nt*8 + 2*tig + 1] = o[nt][3]*inv1;
        }
    }
    for (int x = tid; x < CC*CIc; x += 128){
        int co = x >> 5, ci = x & 31;
        sW[co*WSTR + ci] = ww[x];
    }
    if (tid < CC) sbb[tid] = wb[tid];
    __syncthreads();

    int co = tid >> 1, grp = tid & 1;    // 2 threads per output channel
    float wreg[CIc];
    #pragma unroll
    for (int ci=0; ci<CIc; ci++) wreg[ci] = sW[co*WSTR + ci];
    float bias = sbb[co];

    float s1 = 0.f, s2 = 0.f;
    float* yp = g_Y + (b*CC + co)*NTOK + rb*64;
    #pragma unroll 4
    for (int i=0; i<32; i++){
        int n = 2*i + grp;
        const float4* o4 = (const float4*)&sO[n*OSTR];
        float y = bias;
        #pragma unroll
        for (int c4=0; c4<CIc/4; c4++){
            float4 ov = o4[c4];
            y += wreg[4*c4]*ov.x + wreg[4*c4+1]*ov.y
               + wreg[4*c4+2]*ov.z + wreg[4*c4+3]*ov.w;
        }
        yp[n] = y;
        s1 += y; s2 += y*y;
    }
    s1 += __shfl_xor_sync(0xffffffffu, s1, 1);
    s2 += __shfl_xor_sync(0xffffffffu, s2, 1);
    if (grp == 0){
        atomicAdd(&g_S1[co], s1);
        atomicAdd(&g_S2[co], s2);
    }
}

// ================= Kernel E: BN affine + bilinear 64->128 + residual ======
// 2 horizontal output pixels per thread (shared y source columns).
__global__ void __launch_bounds__(256) final_kernel(
    const float* __restrict__ gamma, const float* __restrict__ beta,
    const float* __restrict__ mainf, float* __restrict__ out)
{
    int idx2 = blockIdx.x*256 + threadIdx.x;  // [b][co][i 0..127][m 0..63]
    int m  = idx2 & 63;
    int i  = (idx2 >> 6) & 127;
    int co = (idx2 >> 13) & 63;
    int b  = idx2 >> 19;

    float si = 0.5f*i - 0.25f;
    si = fminf(fmaxf(si, 0.f), 63.f);
    int i0 = (int)si; float wi = si - (float)i0; int i1 = min(i0+1, 63);

    int cm1 = max(m-1, 0), cp1 = min(m+1, 63);
    const float* yp  = g_Y + (b*CC + co)*NTOK;
    const float* r0p = yp + (i0 << 6);
    const float* r1p = yp + (i1 << 6);
    float wi0 = 1.f - wi;
    float ya = r0p[cm1]*wi0 + r1p[cm1]*wi;
    float yb = r0p[m  ]*wi0 + r1p[m  ]*wi;
    float yc = r0p[cp1]*wi0 + r1p[cp1]*wi;
    float ve = 0.25f*ya + 0.75f*yb;    // j = 2m   (m==0 clamps: ya==yb)
    float vo = 0.75f*yb + 0.25f*yc;    // j = 2m+1 (m==63 clamps: yc==yb)

    const float invN = 1.f/(BB*NTOK);
    float mean = g_S1[co]*invN;
    float var  = g_S2[co]*invN - mean*mean;
    float rstd = rsqrtf(var + 1e-5f);
    float gsc = rstd*gamma[co];
    float bsc = beta[co] - mean*gsc;

    int base = ((b*CC + co)*HM + i)*HM + 2*m;
    float2 mo = *(const float2*)&mainf[base];
    float2 res;
    res.x = ve*gsc + bsc + mo.x;
    res.y = vo*gsc + bsc + mo.y;
    *(float2*)&out[base] = res;
}

// ======================= launch =======================
extern "C" void kernel_launch(void* const* d_in, const int* in_sizes, int n_in,
                              void* d_out, int out_size)
{
    const float* mainf = (const float*)d_in[0];
    const float* cross = (const float*)d_in[1];
    const float* gw    = (const float*)d_in[2];
    const float* gb    = (const float*)d_in[3];
    const float* tw    = (const float*)d_in[4];
    const float* tb    = (const float*)d_in[5];
    const float* pw    = (const float*)d_in[6];
    const float* pb    = (const float*)d_in[7];
    const float* ww    = (const float*)d_in[8];
    const float* wb    = (const float*)d_in[9];
    const float* gamma = (const float*)d_in[10];
    const float* beta  = (const float*)d_in[11];
    float* out = (float*)d_out;

    qkv_kernel<<<(BB*NTOK)/128, 128>>>(mainf, cross, gw, gb, tw, tb, pw, pb);
    flash_kernel<<<dim3(NTOK/64, BB), 128>>>(ww, wb);
    final_kernel<<<(BB*CC*HM*64)/256, 256>>>(gamma, beta, mainf, out);
}

// round 14
// speedup vs baseline: 1.6659x; 1.1855x over previous
#include <cuda_runtime.h>
#include <cuda_fp16.h>
#include <cstdint>

#define BB 4
#define CC 64
#define CIc 32
#define HM 128
#define HC 64
#define NTOK (HC*HC)   /* 4096 */
#define LOG2E 1.4426950408889634f

// -------- scratch (static device globals; no allocation) --------
__device__ uint32_t g_QH[BB*NTOK*16];     // 1 MB: fp16x2 words, [b][token][featpair]
__device__ uint32_t g_KHT[BB*64*16*64];   // 1 MB: [b][tile][featpair d2][token-in-tile]
__device__ __half   g_VT[BB*CIc*NTOK];    // 1 MB: [b][dim][token]
__device__ float    g_Y[BB*CC*NTOK];      // 4 MB
__device__ float    g_S1[CC], g_S2[CC];   // BN partial sums

__device__ __forceinline__ float ex2(float x){
    float r; asm("ex2.approx.f32 %0, %1;" : "=f"(r) : "f"(x));
    return r;
}

__device__ __forceinline__ uint32_t pk_f16(float lo, float hi){
    uint32_t r; asm("cvt.rn.f16x2.f32 %0, %1, %2;" : "=r"(r) : "f"(hi), "f"(lo));
    return r;
}

// non-volatile: register-only, lets ptxas pipeline LDS across MMAs.
__device__ __forceinline__ void mma_f16(float c[4], const uint32_t a[4],
                                        uint32_t b0, uint32_t b1){
    asm("mma.sync.aligned.m16n8k16.row.col.f32.f16.f16.f32 "
        "{%0,%1,%2,%3}, {%4,%5,%6,%7}, {%8,%9}, {%0,%1,%2,%3};"
        : "+f"(c[0]), "+f"(c[1]), "+f"(c[2]), "+f"(c[3])
        : "r"(a[0]), "r"(a[1]), "r"(a[2]), "r"(a[3]), "r"(b0), "r"(b1));
}

// ================= Kernel A: Q,K,V preparation (R9 + cross-batch prefetch) =
// 128 CTAs x 128 threads. Pass 1: merged Q+K over cross; pass 2: V from main.
// Each batch's inputs are prefetched into a 2nd register set during the
// previous batch's FMA block, hiding L2/DRAM latency behind compute.
__global__ void __launch_bounds__(128) qkv_kernel(
    const float* __restrict__ mainf, const float* __restrict__ cross,
    const float* __restrict__ gw, const float* __restrict__ gb,
    const float* __restrict__ tw, const float* __restrict__ tb,
    const float* __restrict__ pw, const float* __restrict__ pb)
{
    __shared__ float swq[CC*CIc], swk[CC*CIc], swv[CC*CIc];
    __shared__ float sbq[CIc], sbk[CIc], sbv[CIc];
    int tid = threadIdx.x;
    if (blockIdx.x == 0 && tid < CC){ g_S1[tid] = 0.f; g_S2[tid] = 0.f; }
    for (int x = tid; x < CC*CIc; x += 128){
        int ci = x & 31, c = x >> 5;       // smem layout [c][ci]
        swq[x] = gw[ci*CC + c];
        swk[x] = tw[ci*CC + c];
        swv[x] = pw[ci*CC + c];
    }
    if (tid < CIc){ sbq[tid]=gb[tid]; sbk[tid]=tb[tid]; sbv[tid]=pb[tid]; }
    __syncthreads();

    int idx = blockIdx.x*128 + tid;        // 0..16383
    int b = idx >> 12, n = idx & 4095;
    const float* cr = cross + (b*CC)*NTOK + n;

    // ---- pass 1: Q and K together (one read of cross; pipelined batches) --
    float aq[CIc], ak[CIc];
    #pragma unroll
    for (int i=0;i<CIc;i++){ aq[i] = sbq[i]; ak[i] = sbk[i]; }
    float xc[8], xn[8];
    #pragma unroll
    for (int j=0;j<8;j++) xc[j] = cr[j*NTOK];
    #pragma unroll 1
    for (int c8=0; c8<8; c8++){
        if (c8 < 7){
            #pragma unroll
            for (int j=0;j<8;j++) xn[j] = cr[((c8+1)*8 + j)*NTOK];
        }
        #pragma unroll
        for (int j=0;j<8;j++){
            int c = c8*8 + j;
            const float4* wq4 = (const float4*)&swq[c*CIc];
            const float4* wk4 = (const float4*)&swk[c*CIc];
            #pragma unroll
            for (int i=0;i<CIc/4;i++){
                float4 wq = wq4[i], wk = wk4[i];
                aq[4*i+0] += wq.x*xc[j]; aq[4*i+1] += wq.y*xc[j];
                aq[4*i+2] += wq.z*xc[j]; aq[4*i+3] += wq.w*xc[j];
                ak[4*i+0] += wk.x*xc[j]; ak[4*i+1] += wk.y*xc[j];
                ak[4*i+2] += wk.z*xc[j]; ak[4*i+3] += wk.w*xc[j];
            }
        }
        #pragma unroll
        for (int j=0;j<8;j++) xc[j] = xn[j];
    }
    {   // Q: [token][16 featpair words], fp16, pre-scaled by log2e
        uint4* qo = (uint4*)(g_QH + idx*16);
        #pragma unroll
        for (int w4=0; w4<4; w4++){
            uint4 v;
            v.x = pk_f16(aq[8*w4+0]*LOG2E, aq[8*w4+1]*LOG2E);
            v.y = pk_f16(aq[8*w4+2]*LOG2E, aq[8*w4+3]*LOG2E);
            v.z = pk_f16(aq[8*w4+4]*LOG2E, aq[8*w4+5]*LOG2E);
            v.w = pk_f16(aq[8*w4+6]*LOG2E, aq[8*w4+7]*LOG2E);
            qo[w4] = v;
        }
        // K: tile-transposed [b][tile][d2][token-in-tile]
        uint32_t* ko = g_KHT + ((b*64 + (n>>6))*16)*64 + (n&63);
        #pragma unroll
        for (int d2=0; d2<16; d2++) ko[d2*64] = pk_f16(ak[2*d2], ak[2*d2+1]);
    }

    // ---- pass 2: V (avg-pool 2x2 of main, then phi), pipelined batches ----
    float av[CIc];
    #pragma unroll
    for (int i=0;i<CIc;i++) av[i] = sbv[i];
    int i2 = (n>>6)<<1, j2 = (n&63)<<1;
    const float* mb = mainf + (b*CC)*HM*HM + i2*HM + j2;
    float2 t0[4], t1[4], u0[4], u1[4];
    #pragma unroll
    for (int j=0;j<4;j++){
        t0[j] = *(const float2*)&mb[j*HM*HM];
        t1[j] = *(const float2*)&mb[j*HM*HM + HM];
    }
    #pragma unroll 1
    for (int c4=0; c4<16; c4++){
        if (c4 < 15){
            #pragma unroll
            for (int j=0;j<4;j++){
                int c = (c4+1)*4 + j;
                u0[j] = *(const float2*)&mb[c*HM*HM];
                u1[j] = *(const float2*)&mb[c*HM*HM + HM];
            }
        }
        #pragma unroll
        for (int j=0;j<4;j++){
            int c = c4*4 + j;
            float xcv = 0.25f*(t0[j].x + t0[j].y + t1[j].x + t1[j].y);
            const float4* w4 = (const float4*)&swv[c*CIc];
            #pragma unroll
            for (int i=0;i<CIc/4;i++){
                float4 w = w4[i];
                av[4*i+0] += w.x*xcv; av[4*i+1] += w.y*xcv;
                av[4*i+2] += w.z*xcv; av[4*i+3] += w.w*xcv;
            }
        }
        #pragma unroll
        for (int j=0;j<4;j++){ t0[j] = u0[j]; t1[j] = u1[j]; }
    }
    {
        __half* o = g_VT + b*CIc*NTOK + n;
        #pragma unroll
        for (int i=0;i<CIc;i++) o[i*NTOK] = __float2half(av[i]);
    }
}

// ================= Kernel B: flash attention v5 (R9-proven, BM=128) =======
// grid (32, 4), 256 threads (8 warps x 16 rows). BM=128, BN=64, d=32.
// QK^T fp16 m16n8k16 (K pre-transposed in global); softmax without max;
// PV fp16 (S C-frag == A-frag); fused epilogue Y=W*O + BN partial sums.
#define KHSTR 72   /* sKH: [16 featpairs][64 token words]; 72%32==8 -> bank=8*tig+gi CF */
#define VWSTR 36   /* sVW: [32 dims][32 words=64 f16 tokens]; bank=4*gi+tig CF */
#define OSTR  36
#define WSTR  33
#define SMEMF (128*OSTR + CC*WSTR + CC)   /* epilogue max user: 6784 floats; tiles need 4608 */
__global__ void __launch_bounds__(256) flash_kernel(
    const float* __restrict__ ww, const float* __restrict__ wb)
{
    __shared__ float smem_f[SMEMF];

    int b = blockIdx.y, rb = blockIdx.x;
    int tid = threadIdx.x;
    int lane = tid & 31;
    int gi = lane >> 2, tig = lane & 3;
    int warp = tid >> 5;

    const uint32_t* Qw  = g_QH + b*NTOK*16;
    const uint32_t* Kht = g_KHT + (b*64)*16*64;
    const __half*   Vbt = g_VT + b*CIc*NTOK;

    uint32_t* sKH0 = (uint32_t*)smem_f;            // 2 x 16*KHSTR words
    uint32_t* sVW0 = sKH0 + 2*16*KHSTR;            // 2 x 32*VWSTR words

    int r0 = rb*128 + warp*16 + gi;      // rows r0 and r0+8

    // Q fragments: fp16 pairs, log2e-scaled
    uint32_t qf[2][4];
    #pragma unroll
    for (int kt=0; kt<2; kt++){
        qf[kt][0] = Qw[(r0  )*16 + 8*kt + tig    ];
        qf[kt][1] = Qw[(r0+8)*16 + 8*kt + tig    ];
        qf[kt][2] = Qw[(r0  )*16 + 8*kt + tig + 4];
        qf[kt][3] = Qw[(r0+8)*16 + 8*kt + tig + 4];
    }

    float o[4][4];
    #pragma unroll
    for (int nt=0;nt<4;nt++){ o[nt][0]=0.f;o[nt][1]=0.f;o[nt][2]=0.f;o[nt][3]=0.f; }
    float l0=0.f, l1=0.f;

    // tile-load index patterns (one uint4 per thread for each of K and V)
    int krow = tid >> 4, kwg = tid & 15;   // K: featpair row, word group
    int vd = tid >> 3,   vt = tid & 7;     // V: dim, token-octet

    // ---- prologue: tile 0 into buffer 0 ----
    {
        uint4 kf = *(const uint4*)(Kht + krow*64 + kwg*4);
        uint4 vf = *(const uint4*)(Vbt + vd*NTOK + vt*8);
        *(uint4*)&sKH0[krow*KHSTR + kwg*4] = kf;
        *(uint4*)&sVW0[vd*VWSTR + vt*4] = vf;
    }

    for (int it=0; it<NTOK/64; it++){
        int buf = it & 1;
        uint4 kf, vf;
        if (it < NTOK/64 - 1){
            int tn = it + 1;
            kf = *(const uint4*)(Kht + (tn*16 + krow)*64 + kwg*4);
            vf = *(const uint4*)(Vbt + vd*NTOK + tn*64 + vt*8);
        }
        __syncthreads();

        const uint32_t* kh = sKH0 + buf*(16*KHSTR);
        const uint32_t* vW = sVW0 + buf*(32*VWSTR);

        // ---- S = Q K^T (16 x 64 per warp), fp16 MMA, log2 units ----
        float s[8][4];
        #pragma unroll
        for (int nt=0;nt<8;nt++){ s[nt][0]=0.f;s[nt][1]=0.f;s[nt][2]=0.f;s[nt][3]=0.f; }
        #pragma unroll
        for (int kt=0; kt<2; kt++){
            #pragma unroll
            for (int nt=0; nt<8; nt++){
                uint32_t b0 = kh[(8*kt + tig    )*KHSTR + nt*8 + gi];
                uint32_t b1 = kh[(8*kt + tig + 4)*KHSTR + nt*8 + gi];
                mma_f16(s[nt], qf[kt], b0, b1);
            }
        }

        // ---- softmax numerator (no max subtraction; logits bounded) ----
        #pragma unroll
        for (int nt=0;nt<8;nt++){
            float p0 = ex2(s[nt][0]), p1 = ex2(s[nt][1]);
            float p2 = ex2(s[nt][2]), p3 = ex2(s[nt][3]);
            l0 += p0 + p1; l1 += p2 + p3;
            s[nt][0]=p0; s[nt][1]=p1; s[nt][2]=p2; s[nt][3]=p3;
        }

        // ---- O += P V : fp16 MMA; S C-frag == PV A-frag ----
        #pragma unroll
        for (int kt=0; kt<4; kt++){
            uint32_t a[4];
            a[0] = pk_f16(s[2*kt  ][0], s[2*kt  ][1]);
            a[1] = pk_f16(s[2*kt  ][2], s[2*kt  ][3]);
            a[2] = pk_f16(s[2*kt+1][0], s[2*kt+1][1]);
            a[3] = pk_f16(s[2*kt+1][2], s[2*kt+1][3]);
            #pragma unroll
            for (int nt=0; nt<4; nt++){
                uint32_t b0 = vW[(nt*8+gi)*VWSTR + kt*8 + tig    ];
                uint32_t b1 = vW[(nt*8+gi)*VWSTR + kt*8 + tig + 4];
                mma_f16(o[nt], a, b0, b1);
            }
        }

        // ---- store prefetched tile into the other buffer ----
        if (it < NTOK/64 - 1){
            *(uint4*)&sKH0[(buf^1)*(16*KHSTR) + krow*KHSTR + kwg*4] = kf;
            *(uint4*)&sVW0[(buf^1)*(32*VWSTR) + vd*VWSTR + vt*4] = vf;
        }
    }

    // ---- finalize softmax denominators ----
    l0 += __shfl_xor_sync(0xffffffffu, l0, 1);
    l0 += __shfl_xor_sync(0xffffffffu, l0, 2);
    l1 += __shfl_xor_sync(0xffffffffu, l1, 1);
    l1 += __shfl_xor_sync(0xffffffffu, l1, 2);
    float inv0 = 1.f/l0, inv1 = 1.f/l1;

    // ================= fused epilogue: Y = W*O + b, BN partial sums =======
    __syncthreads();   // tiles no longer needed; repurpose smem
    float* sO  = smem_f;                 // [128][OSTR]
    float* sW  = smem_f + 128*OSTR;      // [64][WSTR]
    float* sbb = sW + CC*WSTR;           // [64]

    {   // store normalized O tile (block-local rows)
        int row0 = warp*16 + gi;
        #pragma unroll
        for (int nt=0; nt<4; nt++){
            sO[(row0  )*OSTR + nt*8 + 2*tig    ] = o[nt][0]*inv0;
            sO[(row0  )*OSTR + nt*8 + 2*tig + 1] = o[nt][1]*inv0;
            sO[(row0+8)*OSTR + nt*8 + 2*tig    ] = o[nt][2]*inv1;
            sO[(row0+8)*OSTR + nt*8 + 2*tig + 1] = o[nt][3]*inv1;
        }
    }
    for (int x = tid; x < CC*CIc; x += 256){
        int co = x >> 5, ci = x & 31;
        sW[co*WSTR + ci] = ww[x];
    }
    if (tid < CC) sbb[tid] = wb[tid];
    __syncthreads();

    int co = tid >> 2, grp = tid & 3;
    float wreg[CIc];
    #pragma unroll
    for (int ci=0; ci<CIc; ci++) wreg[ci] = sW[co*WSTR + ci];
    float bias = sbb[co];

    float s1 = 0.f, s2 = 0.f;
    float* yp = g_Y + (b*CC + co)*NTOK + rb*128;
    #pragma unroll 4
    for (int i=0; i<32; i++){
        int n = 4*i + grp;
        const float4* o4 = (const float4*)&sO[n*OSTR];
        float y = bias;
        #pragma unroll
        for (int c4=0; c4<CIc/4; c4++){
            float4 ov = o4[c4];
            y += wreg[4*c4]*ov.x + wreg[4*c4+1]*ov.y
               + wreg[4*c4+2]*ov.z + wreg[4*c4+3]*ov.w;
        }
        yp[n] = y;
        s1 += y; s2 += y*y;
    }
    s1 += __shfl_xor_sync(0xffffffffu, s1, 1);
    s1 += __shfl_xor_sync(0xffffffffu, s1, 2);
    s2 += __shfl_xor_sync(0xffffffffu, s2, 1);
    s2 += __shfl_xor_sync(0xffffffffu, s2, 2);
    if (grp == 0){
        atomicAdd(&g_S1[co], s1);
        atomicAdd(&g_S2[co], s2);
    }
}

// ================= Kernel E: BN affine + bilinear 64->128 + residual ======
// 2 horizontal output pixels per thread (shared y source columns).
__global__ void __launch_bounds__(256) final_kernel(
    const float* __restrict__ gamma, const float* __restrict__ beta,
    const float* __restrict__ mainf, float* __restrict__ out)
{
    int idx2 = blockIdx.x*256 + threadIdx.x;  // [b][co][i 0..127][m 0..63]
    int m  = idx2 & 63;
    int i  = (idx2 >> 6) & 127;
    int co = (idx2 >> 13) & 63;
    int b  = idx2 >> 19;

    float si = 0.5f*i - 0.25f;
    si = fminf(fmaxf(si, 0.f), 63.f);
    int i0 = (int)si; float wi = si - (float)i0; int i1 = min(i0+1, 63);

    int cm1 = max(m-1, 0), cp1 = min(m+1, 63);
    const float* yp  = g_Y + (b*CC + co)*NTOK;
    const float* r0p = yp + (i0 << 6);
    const float* r1p = yp + (i1 << 6);
    float wi0 = 1.f - wi;
    float ya = r0p[cm1]*wi0 + r1p[cm1]*wi;
    float yb = r0p[m  ]*wi0 + r1p[m  ]*wi;
    float yc = r0p[cp1]*wi0 + r1p[cp1]*wi;
    float ve = 0.25f*ya + 0.75f*yb;    // j = 2m   (m==0 clamps: ya==yb)
    float vo = 0.75f*yb + 0.25f*yc;    // j = 2m+1 (m==63 clamps: yc==yb)

    const float invN = 1.f/(BB*NTOK);
    float mean = g_S1[co]*invN;
    float var  = g_S2[co]*invN - mean*mean;
    float rstd = rsqrtf(var + 1e-5f);
    float gsc = rstd*gamma[co];
    float bsc = beta[co] - mean*gsc;

    int base = ((b*CC + co)*HM + i)*HM + 2*m;
    float2 mo = *(const float2*)&mainf[base];
    float2 res;
    res.x = ve*gsc + bsc + mo.x;
    res.y = vo*gsc + bsc + mo.y;
    *(float2*)&out[base] = res;
}

// ======================= launch =======================
extern "C" void kernel_launch(void* const* d_in, const int* in_sizes, int n_in,
                              void* d_out, int out_size)
{
    const float* mainf = (const float*)d_in[0];
    const float* cross = (const float*)d_in[1];
    const float* gw    = (const float*)d_in[2];
    const float* gb    = (const float*)d_in[3];
    const float* tw    = (const float*)d_in[4];
    const float* tb    = (const float*)d_in[5];
    const float* pw    = (const float*)d_in[6];
    const float* pb    = (const float*)d_in[7];
    const float* ww    = (const float*)d_in[8];
    const float* wb    = (const float*)d_in[9];
    const float* gamma = (const float*)d_in[10];
    const float* beta  = (const float*)d_in[11];
    float* out = (float*)d_out;

    qkv_kernel<<<(BB*NTOK)/128, 128>>>(mainf, cross, gw, gb, tw, tb, pw, pb);
    flash_kernel<<<dim3(NTOK/128, BB), 256>>>(ww, wb);
    final_kernel<<<(BB*CC*HM*64)/256, 256>>>(gamma, beta, mainf, out);
}

// round 15
// speedup vs baseline: 1.9871x; 1.1928x over previous
#include <cuda_runtime.h>
#include <cuda_fp16.h>
#include <cstdint>

#define BB 4
#define CC 64
#define CIc 32
#define HM 128
#define HC 64
#define NTOK (HC*HC)   /* 4096 */
#define LOG2E 1.4426950408889634f

// -------- scratch (static device globals; no allocation) --------
__device__ uint32_t g_QH[BB*NTOK*16];     // 1 MB: fp16x2 words, [b][token][featpair]
__device__ uint32_t g_KHT[BB*64*16*64];   // 1 MB: [b][tile][featpair d2][token-in-tile]
__device__ __half   g_VT[BB*CIc*NTOK];    // 1 MB: [b][dim][token]
__device__ float    g_Y[BB*CC*NTOK];      // 4 MB
__device__ float    g_S1[CC], g_S2[CC];   // BN partial sums

__device__ __forceinline__ uint32_t pk_f16(float lo, float hi){
    uint32_t r; asm("cvt.rn.f16x2.f32 %0, %1, %2;" : "=r"(r) : "f"(hi), "f"(lo));
    return r;
}

// non-volatile: register-only, lets ptxas pipeline LDS across MMAs.
__device__ __forceinline__ void mma_f16(float c[4], const uint32_t a[4],
                                        uint32_t b0, uint32_t b1){
    asm("mma.sync.aligned.m16n8k16.row.col.f32.f16.f16.f32 "
        "{%0,%1,%2,%3}, {%4,%5,%6,%7}, {%8,%9}, {%0,%1,%2,%3};"
        : "+f"(c[0]), "+f"(c[1]), "+f"(c[2]), "+f"(c[3])
        : "r"(a[0]), "r"(a[1]), "r"(a[2]), "r"(a[3]), "r"(b0), "r"(b1));
}

// ================= Kernel A: Q,K,V preparation (R14-proven) ===============
// 128 CTAs x 128 threads. Pass 1: merged Q+K over cross; pass 2: V from main.
// Cross-batch register prefetch hides L2/DRAM latency behind FMA blocks.
__global__ void __launch_bounds__(128) qkv_kernel(
    const float* __restrict__ mainf, const float* __restrict__ cross,
    const float* __restrict__ gw, const float* __restrict__ gb,
    const float* __restrict__ tw, const float* __restrict__ tb,
    const float* __restrict__ pw, const float* __restrict__ pb)
{
    __shared__ float swq[CC*CIc], swk[CC*CIc], swv[CC*CIc];
    __shared__ float sbq[CIc], sbk[CIc], sbv[CIc];
    int tid = threadIdx.x;
    if (blockIdx.x == 0 && tid < CC){ g_S1[tid] = 0.f; g_S2[tid] = 0.f; }
    for (int x = tid; x < CC*CIc; x += 128){
        int ci = x & 31, c = x >> 5;       // smem layout [c][ci]
        swq[x] = gw[ci*CC + c];
        swk[x] = tw[ci*CC + c];
        swv[x] = pw[ci*CC + c];
    }
    if (tid < CIc){ sbq[tid]=gb[tid]; sbk[tid]=tb[tid]; sbv[tid]=pb[tid]; }
    __syncthreads();

    int idx = blockIdx.x*128 + tid;        // 0..16383
    int b = idx >> 12, n = idx & 4095;
    const float* cr = cross + (b*CC)*NTOK + n;

    // ---- pass 1: Q and K together (one read of cross; pipelined batches) --
    float aq[CIc], ak[CIc];
    #pragma unroll
    for (int i=0;i<CIc;i++){ aq[i] = sbq[i]; ak[i] = sbk[i]; }
    float xc[8], xn[8];
    #pragma unroll
    for (int j=0;j<8;j++) xc[j] = cr[j*NTOK];
    #pragma unroll 1
    for (int c8=0; c8<8; c8++){
        if (c8 < 7){
            #pragma unroll
            for (int j=0;j<8;j++) xn[j] = cr[((c8+1)*8 + j)*NTOK];
        }
        #pragma unroll
        for (int j=0;j<8;j++){
            int c = c8*8 + j;
            const float4* wq4 = (const float4*)&swq[c*CIc];
            const float4* wk4 = (const float4*)&swk[c*CIc];
            #pragma unroll
            for (int i=0;i<CIc/4;i++){
                float4 wq = wq4[i], wk = wk4[i];
                aq[4*i+0] += wq.x*xc[j]; aq[4*i+1] += wq.y*xc[j];
                aq[4*i+2] += wq.z*xc[j]; aq[4*i+3] += wq.w*xc[j];
                ak[4*i+0] += wk.x*xc[j]; ak[4*i+1] += wk.y*xc[j];
                ak[4*i+2] += wk.z*xc[j]; ak[4*i+3] += wk.w*xc[j];
            }
        }
        #pragma unroll
        for (int j=0;j<8;j++) xc[j] = xn[j];
    }
    {   // Q: [token][16 featpair words], fp16, pre-scaled by log2e
        uint4* qo = (uint4*)(g_QH + idx*16);
        #pragma unroll
        for (int w4=0; w4<4; w4++){
            uint4 v;
            v.x = pk_f16(aq[8*w4+0]*LOG2E, aq[8*w4+1]*LOG2E);
            v.y = pk_f16(aq[8*w4+2]*LOG2E, aq[8*w4+3]*LOG2E);
            v.z = pk_f16(aq[8*w4+4]*LOG2E, aq[8*w4+5]*LOG2E);
            v.w = pk_f16(aq[8*w4+6]*LOG2E, aq[8*w4+7]*LOG2E);
            qo[w4] = v;
        }
        // K: tile-transposed [b][tile][d2][token-in-tile]
        uint32_t* ko = g_KHT + ((b*64 + (n>>6))*16)*64 + (n&63);
        #pragma unroll
        for (int d2=0; d2<16; d2++) ko[d2*64] = pk_f16(ak[2*d2], ak[2*d2+1]);
    }

    // ---- pass 2: V (avg-pool 2x2 of main, then phi), pipelined batches ----
    float av[CIc];
    #pragma unroll
    for (int i=0;i<CIc;i++) av[i] = sbv[i];
    int i2 = (n>>6)<<1, j2 = (n&63)<<1;
    const float* mb = mainf + (b*CC)*HM*HM + i2*HM + j2;
    float2 t0[4], t1[4], u0[4], u1[4];
    #pragma unroll
    for (int j=0;j<4;j++){
        t0[j] = *(const float2*)&mb[j*HM*HM];
        t1[j] = *(const float2*)&mb[j*HM*HM + HM];
    }
    #pragma unroll 1
    for (int c4=0; c4<16; c4++){
        if (c4 < 15){
            #pragma unroll
            for (int j=0;j<4;j++){
                int c = (c4+1)*4 + j;
                u0[j] = *(const float2*)&mb[c*HM*HM];
                u1[j] = *(const float2*)&mb[c*HM*HM + HM];
            }
        }
        #pragma unroll
        for (int j=0;j<4;j++){
            int c = c4*4 + j;
            float xcv = 0.25f*(t0[j].x + t0[j].y + t1[j].x + t1[j].y);
            const float4* w4 = (const float4*)&swv[c*CIc];
            #pragma unroll
            for (int i=0;i<CIc/4;i++){
                float4 w = w4[i];
                av[4*i+0] += w.x*xcv; av[4*i+1] += w.y*xcv;
                av[4*i+2] += w.z*xcv; av[4*i+3] += w.w*xcv;
            }
        }
        #pragma unroll
        for (int j=0;j<4;j++){ t0[j] = u0[j]; t1[j] = u1[j]; }
    }
    {
        __half* o = g_VT + b*CIc*NTOK + n;
        #pragma unroll
        for (int i=0;i<CIc;i++) o[i*NTOK] = __float2half(av[i]);
    }
}

// ================= Kernel B: flash attention v7 (f16 softmax + ones-MMA) ==
// grid (32, 4), 256 threads (8 warps x 16 rows). BM=128, BN=64, d=32.
// QK^T fp16 m16n8k16; softmax: pack logits to f16x2 then ex2.approx.f16x2
// (half the MUFU work); row sums via an extra MMA against a constant
// ones-column B-fragment (no FADD chain); PV fp16; fused epilogue.
#define KHSTR 72   /* sKH: [16 featpairs][64 token words]; 72%32==8 -> bank=8*tig+gi CF */
#define VWSTR 36   /* sVW: [32 dims][32 words=64 f16 tokens]; bank=4*gi+tig CF */
#define OSTR  36
#define WSTR  33
#define SMEMF (128*OSTR + CC*WSTR + CC)   /* epilogue max user: 6784 floats; tiles need 4608 */
__global__ void __launch_bounds__(256) flash_kernel(
    const float* __restrict__ ww, const float* __restrict__ wb)
{
    __shared__ float smem_f[SMEMF];

    int b = blockIdx.y, rb = blockIdx.x;
    int tid = threadIdx.x;
    int lane = tid & 31;
    int gi = lane >> 2, tig = lane & 3;
    int warp = tid >> 5;

    const uint32_t* Qw  = g_QH + b*NTOK*16;
    const uint32_t* Kht = g_KHT + (b*64)*16*64;
    const __half*   Vbt = g_VT + b*CIc*NTOK;

    uint32_t* sKH0 = (uint32_t*)smem_f;            // 2 x 16*KHSTR words
    uint32_t* sVW0 = sKH0 + 2*16*KHSTR;            // 2 x 32*VWSTR words

    int r0 = rb*128 + warp*16 + gi;      // rows r0 and r0+8

    // Q fragments: fp16 pairs, log2e-scaled
    uint32_t qf[2][4];
    #pragma unroll
    for (int kt=0; kt<2; kt++){
        qf[kt][0] = Qw[(r0  )*16 + 8*kt + tig    ];
        qf[kt][1] = Qw[(r0+8)*16 + 8*kt + tig    ];
        qf[kt][2] = Qw[(r0  )*16 + 8*kt + tig + 4];
        qf[kt][3] = Qw[(r0+8)*16 + 8*kt + tig + 4];
    }

    float o[4][4];
    #pragma unroll
    for (int nt=0;nt<4;nt++){ o[nt][0]=0.f;o[nt][1]=0.f;o[nt][2]=0.f;o[nt][3]=0.f; }
    float lacc[4] = {0.f, 0.f, 0.f, 0.f};   // ones-column accumulator (rowsum at tig==0)

    // ones-column B-fragment: col 0 of the extra n-group = 1.0 for all 16 k
    uint32_t ones = (gi == 0) ? 0x3C003C00u : 0u;

    // tile-load index patterns (one uint4 per thread for each of K and V)
    int krow = tid >> 4, kwg = tid & 15;   // K: featpair row, word group
    int vd = tid >> 3,   vt = tid & 7;     // V: dim, token-octet

    // ---- prologue: tile 0 into buffer 0 ----
    {
        uint4 kf = *(const uint4*)(Kht + krow*64 + kwg*4);
        uint4 vf = *(const uint4*)(Vbt + vd*NTOK + vt*8);
        *(uint4*)&sKH0[krow*KHSTR + kwg*4] = kf;
        *(uint4*)&sVW0[vd*VWSTR + vt*4] = vf;
    }

    for (int it=0; it<NTOK/64; it++){
        int buf = it & 1;
        uint4 kf, vf;
        if (it < NTOK/64 - 1){
            int tn = it + 1;
            kf = *(const uint4*)(Kht + (tn*16 + krow)*64 + kwg*4);
            vf = *(const uint4*)(Vbt + vd*NTOK + tn*64 + vt*8);
        }
        __syncthreads();

        const uint32_t* kh = sKH0 + buf*(16*KHSTR);
        const uint32_t* vW = sVW0 + buf*(32*VWSTR);

        // ---- S = Q K^T (16 x 64 per warp), fp16 MMA, log2 units ----
        float s[8][4];
        #pragma unroll
        for (int nt=0;nt<8;nt++){ s[nt][0]=0.f;s[nt][1]=0.f;s[nt][2]=0.f;s[nt][3]=0.f; }
        #pragma unroll
        for (int kt=0; kt<2; kt++){
            #pragma unroll
            for (int nt=0; nt<8; nt++){
                uint32_t b0 = kh[(8*kt + tig    )*KHSTR + nt*8 + gi];
                uint32_t b1 = kh[(8*kt + tig + 4)*KHSTR + nt*8 + gi];
                mma_f16(s[nt], qf[kt], b0, b1);
            }
        }

        // ---- softmax numerator in fp16: pack logits, then packed ex2 ----
        uint32_t ph[16];
        #pragma unroll
        for (int kt=0; kt<4; kt++){
            ph[4*kt+0] = pk_f16(s[2*kt  ][0], s[2*kt  ][1]);
            ph[4*kt+1] = pk_f16(s[2*kt  ][2], s[2*kt  ][3]);
            ph[4*kt+2] = pk_f16(s[2*kt+1][0], s[2*kt+1][1]);
            ph[4*kt+3] = pk_f16(s[2*kt+1][2], s[2*kt+1][3]);
        }
        #pragma unroll
        for (int i=0;i<16;i++)
            asm("ex2.approx.f16x2 %0, %0;" : "+r"(ph[i]));

        // ---- O += P V, rowsum += P 1 : fp16 MMA; P words are the A-frags --
        #pragma unroll
        for (int kt=0; kt<4; kt++){
            const uint32_t* a = &ph[4*kt];
            #pragma unroll
            for (int nt=0; nt<4; nt++){
                uint32_t b0 = vW[(nt*8+gi)*VWSTR + kt*8 + tig    ];
                uint32_t b1 = vW[(nt*8+gi)*VWSTR + kt*8 + tig + 4];
                mma_f16(o[nt], a, b0, b1);
            }
            mma_f16(lacc, a, ones, ones);
        }

        // ---- store prefetched tile into the other buffer ----
        if (it < NTOK/64 - 1){
            *(uint4*)&sKH0[(buf^1)*(16*KHSTR) + krow*KHSTR + kwg*4] = kf;
            *(uint4*)&sVW0[(buf^1)*(32*VWSTR) + vd*VWSTR + vt*4] = vf;
        }
    }

    // ---- finalize: row sums live in lacc[0]/lacc[2] of tig==0 lanes ----
    int qbase = lane & ~3;
    float l0 = __shfl_sync(0xffffffffu, lacc[0], qbase);
    float l1 = __shfl_sync(0xffffffffu, lacc[2], qbase);
    float inv0 = 1.f/l0, inv1 = 1.f/l1;

    // ================= fused epilogue: Y = W*O + b, BN partial sums =======
    __syncthreads();   // tiles no longer needed; repurpose smem
    float* sO  = smem_f;                 // [128][OSTR]
    float* sW  = smem_f + 128*OSTR;      // [64][WSTR]
    float* sbb = sW + CC*WSTR;           // [64]

    {   // store normalized O tile (block-local rows)
        int row0 = warp*16 + gi;
        #pragma unroll
        for (int nt=0; nt<4; nt++){
            sO[(row0  )*OSTR + nt*8 + 2*tig    ] = o[nt][0]*inv0;
            sO[(row0  )*OSTR + nt*8 + 2*tig + 1] = o[nt][1]*inv0;
            sO[(row0+8)*OSTR + nt*8 + 2*tig    ] = o[nt][2]*inv1;
            sO[(row0+8)*OSTR + nt*8 + 2*tig + 1] = o[nt][3]*inv1;
        }
    }
    for (int x = tid; x < CC*CIc; x += 256){
        int co = x >> 5, ci = x & 31;
        sW[co*WSTR + ci] = ww[x];
    }
    if (tid < CC) sbb[tid] = wb[tid];
    __syncthreads();

    int co = tid >> 2, grp = tid & 3;
    float wreg[CIc];
    #pragma unroll
    for (int ci=0; ci<CIc; ci++) wreg[ci] = sW[co*WSTR + ci];
    float bias = sbb[co];

    float s1 = 0.f, s2 = 0.f;
    float* yp = g_Y + (b*CC + co)*NTOK + rb*128;
    #pragma unroll 4
    for (int i=0; i<32; i++){
        int n = 4*i + grp;
        const float4* o4 = (const float4*)&sO[n*OSTR];
        float y = bias;
        #pragma unroll
        for (int c4=0; c4<CIc/4; c4++){
            float4 ov = o4[c4];
            y += wreg[4*c4]*ov.x + wreg[4*c4+1]*ov.y
               + wreg[4*c4+2]*ov.z + wreg[4*c4+3]*ov.w;
        }
        yp[n] = y;
        s1 += y; s2 += y*y;
    }
    s1 += __shfl_xor_sync(0xffffffffu, s1, 1);
    s1 += __shfl_xor_sync(0xffffffffu, s1, 2);
    s2 += __shfl_xor_sync(0xffffffffu, s2, 1);
    s2 += __shfl_xor_sync(0xffffffffu, s2, 2);
    if (grp == 0){
        atomicAdd(&g_S1[co], s1);
        atomicAdd(&g_S2[co], s2);
    }
}

// ================= Kernel E: BN affine + bilinear 64->128 + residual ======
// 2 horizontal output pixels per thread (shared y source columns).
__global__ void __launch_bounds__(256) final_kernel(
    const float* __restrict__ gamma, const float* __restrict__ beta,
    const float* __restrict__ mainf, float* __restrict__ out)
{
    int idx2 = blockIdx.x*256 + threadIdx.x;  // [b][co][i 0..127][m 0..63]
    int m  = idx2 & 63;
    int i  = (idx2 >> 6) & 127;
    int co = (idx2 >> 13) & 63;
    int b  = idx2 >> 19;

    float si = 0.5f*i - 0.25f;
    si = fminf(fmaxf(si, 0.f), 63.f);
    int i0 = (int)si; float wi = si - (float)i0; int i1 = min(i0+1, 63);

    int cm1 = max(m-1, 0), cp1 = min(m+1, 63);
    const float* yp  = g_Y + (b*CC + co)*NTOK;
    const float* r0p = yp + (i0 << 6);
    const float* r1p = yp + (i1 << 6);
    float wi0 = 1.f - wi;
    float ya = r0p[cm1]*wi0 + r1p[cm1]*wi;
    float yb = r0p[m  ]*wi0 + r1p[m  ]*wi;
    float yc = r0p[cp1]*wi0 + r1p[cp1]*wi;
    float ve = 0.25f*ya + 0.75f*yb;    // j = 2m   (m==0 clamps: ya==yb)
    float vo = 0.75f*yb + 0.25f*yc;    // j = 2m+1 (m==63 clamps: yc==yb)

    const float invN = 1.f/(BB*NTOK);
    float mean = g_S1[co]*invN;
    float var  = g_S2[co]*invN - mean*mean;
    float rstd = rsqrtf(var + 1e-5f);
    float gsc = rstd*gamma[co];
    float bsc = beta[co] - mean*gsc;

    int base = ((b*CC + co)*HM + i)*HM + 2*m;
    float2 mo = *(const float2*)&mainf[base];
    float2 res;
    res.x = ve*gsc + bsc + mo.x;
    res.y = vo*gsc + bsc + mo.y;
    *(float2*)&out[base] = res;
}

// ======================= launch =======================
extern "C" void kernel_launch(void* const* d_in, const int* in_sizes, int n_in,
                              void* d_out, int out_size)
{
    const float* mainf = (const float*)d_in[0];
    const float* cross = (const float*)d_in[1];
    const float* gw    = (const float*)d_in[2];
    const float* gb    = (const float*)d_in[3];
    const float* tw    = (const float*)d_in[4];
    const float* tb    = (const float*)d_in[5];
    const float* pw    = (const float*)d_in[6];
    const float* pb    = (const float*)d_in[7];
    const float* ww    = (const float*)d_in[8];
    const float* wb    = (const float*)d_in[9];
    const float* gamma = (const float*)d_in[10];
    const float* beta  = (const float*)d_in[11];
    float* out = (float*)d_out;

    qkv_kernel<<<(BB*NTOK)/128, 128>>>(mainf, cross, gw, gb, tw, tb, pw, pb);
    flash_kernel<<<dim3(NTOK/128, BB), 256>>>(ww, wb);
    final_kernel<<<(BB*CC*HM*64)/256, 256>>>(gamma, beta, mainf, out);
}

// round 16
// speedup vs baseline: 2.1031x; 1.0584x over previous
#include <cuda_runtime.h>
#include <cuda_fp16.h>
#include <cstdint>

#define BB 4
#define CC 64
#define CIc 32
#define HM 128
#define HC 64
#define NTOK (HC*HC)   /* 4096 */
#define LOG2E 1.4426950408889634f

// -------- scratch (static device globals; no allocation) --------
__device__ uint32_t g_QH[BB*NTOK*16];     // 1 MB: fp16x2 words, [b][token][featpair]
__device__ uint32_t g_KHT[BB*64*16*64];   // 1 MB: [b][tile][featpair d2][token-in-tile]
__device__ __half   g_VT[BB*CIc*NTOK];    // 1 MB: [b][dim][token]
__device__ float    g_Y[BB*CC*NTOK];      // 4 MB
__device__ float    g_S1[CC], g_S2[CC];   // BN partial sums

__device__ __forceinline__ uint32_t pk_f16(float lo, float hi){
    uint32_t r; asm("cvt.rn.f16x2.f32 %0, %1, %2;" : "=r"(r) : "f"(hi), "f"(lo));
    return r;
}

// non-volatile: register-only, lets ptxas pipeline LDS across MMAs.
__device__ __forceinline__ void mma_f16(float c[4], const uint32_t a[4],
                                        uint32_t b0, uint32_t b1){
    asm("mma.sync.aligned.m16n8k16.row.col.f32.f16.f16.f32 "
        "{%0,%1,%2,%3}, {%4,%5,%6,%7}, {%8,%9}, {%0,%1,%2,%3};"
        : "+f"(c[0]), "+f"(c[1]), "+f"(c[2]), "+f"(c[3])
        : "r"(a[0]), "r"(a[1]), "r"(a[2]), "r"(a[3]), "r"(b0), "r"(b1));
}

// ================= Kernel A: Q,K,V preparation (v5: in-CTA role split) ====
// 128 CTAs x 384 threads. Threads 0..127 compute Q, 128..255 compute K
// (both read cross — K's reads are L2 hits), 256..383 compute V from main.
// Per-role warp-level load/store patterns identical to the proven R14 code;
// per-thread serial FMA chain halves and warps/SM triple.
__global__ void __launch_bounds__(384) qkv_kernel(
    const float* __restrict__ mainf, const float* __restrict__ cross,
    const float* __restrict__ gw, const float* __restrict__ gb,
    const float* __restrict__ tw, const float* __restrict__ tb,
    const float* __restrict__ pw, const float* __restrict__ pb)
{
    __shared__ float sw[3][CC*CIc];
    __shared__ float sb[3][CIc];
    int tid = threadIdx.x;
    if (blockIdx.x == 0 && tid < CC){ g_S1[tid] = 0.f; g_S2[tid] = 0.f; }
    for (int x = tid; x < CC*CIc; x += 384){
        int ci = x & 31, c = x >> 5;       // smem layout [c][ci]
        sw[0][x] = gw[ci*CC + c];
        sw[1][x] = tw[ci*CC + c];
        sw[2][x] = pw[ci*CC + c];
    }
    if (tid < CIc){ sb[0][tid]=gb[tid]; sb[1][tid]=tb[tid]; sb[2][tid]=pb[tid]; }
    __syncthreads();

    int role = tid >> 7;                   // 0=Q, 1=K, 2=V
    int pt   = tid & 127;                  // pixel slot within CTA
    int idx  = blockIdx.x*128 + pt;        // 0..16383
    int b = idx >> 12, n = idx & 4095;

    const float* wsm = sw[role];
    float acc[CIc];
    #pragma unroll
    for (int i=0;i<CIc;i++) acc[i] = sb[role][i];

    if (role < 2){
        // ---- Q or K from cross (8-ch batches, register prefetch) ----
        const float* cr = cross + (b*CC)*NTOK + n;
        float xc[8], xn[8];
        #pragma unroll
        for (int j=0;j<8;j++) xc[j] = cr[j*NTOK];
        #pragma unroll 1
        for (int c8=0; c8<8; c8++){
            if (c8 < 7){
                #pragma unroll
                for (int j=0;j<8;j++) xn[j] = cr[((c8+1)*8 + j)*NTOK];
            }
            #pragma unroll
            for (int j=0;j<8;j++){
                const float4* w4 = (const float4*)&wsm[(c8*8 + j)*CIc];
                #pragma unroll
                for (int i=0;i<CIc/4;i++){
                    float4 w = w4[i];
                    acc[4*i+0] += w.x*xc[j]; acc[4*i+1] += w.y*xc[j];
                    acc[4*i+2] += w.z*xc[j]; acc[4*i+3] += w.w*xc[j];
                }
            }
            #pragma unroll
            for (int j=0;j<8;j++) xc[j] = xn[j];
        }
        if (role == 0){
            // Q: [token][16 featpair words], fp16, pre-scaled by log2e
            uint4* qo = (uint4*)(g_QH + idx*16);
            #pragma unroll
            for (int w4=0; w4<4; w4++){
                uint4 v;
                v.x = pk_f16(acc[8*w4+0]*LOG2E, acc[8*w4+1]*LOG2E);
                v.y = pk_f16(acc[8*w4+2]*LOG2E, acc[8*w4+3]*LOG2E);
                v.z = pk_f16(acc[8*w4+4]*LOG2E, acc[8*w4+5]*LOG2E);
                v.w = pk_f16(acc[8*w4+6]*LOG2E, acc[8*w4+7]*LOG2E);
                qo[w4] = v;
            }
        } else {
            // K: tile-transposed [b][tile][d2][token-in-tile]
            uint32_t* ko = g_KHT + ((b*64 + (n>>6))*16)*64 + (n&63);
            #pragma unroll
            for (int d2=0; d2<16; d2++) ko[d2*64] = pk_f16(acc[2*d2], acc[2*d2+1]);
        }
    } else {
        // ---- V = phi(avgpool2x2(main)), pipelined 4-ch batches ----
        int i2 = (n>>6)<<1, j2 = (n&63)<<1;
        const float* mb = mainf + (b*CC)*HM*HM + i2*HM + j2;
        float2 t0[4], t1[4], u0[4], u1[4];
        #pragma unroll
        for (int j=0;j<4;j++){
            t0[j] = *(const float2*)&mb[j*HM*HM];
            t1[j] = *(const float2*)&mb[j*HM*HM + HM];
        }
        #pragma unroll 1
        for (int c4=0; c4<16; c4++){
            if (c4 < 15){
                #pragma unroll
                for (int j=0;j<4;j++){
                    int c = (c4+1)*4 + j;
                    u0[j] = *(const float2*)&mb[c*HM*HM];
                    u1[j] = *(const float2*)&mb[c*HM*HM + HM];
                }
            }
            #pragma unroll
            for (int j=0;j<4;j++){
                float xcv = 0.25f*(t0[j].x + t0[j].y + t1[j].x + t1[j].y);
                const float4* w4 = (const float4*)&wsm[(c4*4 + j)*CIc];
                #pragma unroll
                for (int i=0;i<CIc/4;i++){
                    float4 w = w4[i];
                    acc[4*i+0] += w.x*xcv; acc[4*i+1] += w.y*xcv;
                    acc[4*i+2] += w.z*xcv; acc[4*i+3] += w.w*xcv;
                }
            }
            #pragma unroll
            for (int j=0;j<4;j++){ t0[j] = u0[j]; t1[j] = u1[j]; }
        }
        __half* o = g_VT + b*CIc*NTOK + n;
        #pragma unroll
        for (int i=0;i<CIc;i++) o[i*NTOK] = __float2half(acc[i]);
    }
}

// ================= Kernel B: flash attention v7 (f16 softmax + ones-MMA) ==
// grid (32, 4), 256 threads (8 warps x 16 rows). BM=128, BN=64, d=32.
// QK^T fp16 m16n8k16; softmax: pack logits to f16x2 then ex2.approx.f16x2;
// row sums via MMA against a constant ones-column; PV fp16; fused epilogue.
#define KHSTR 72   /* sKH: [16 featpairs][64 token words]; 72%32==8 -> bank=8*tig+gi CF */
#define VWSTR 36   /* sVW: [32 dims][32 words=64 f16 tokens]; bank=4*gi+tig CF */
#define OSTR  36
#define WSTR  33
#define SMEMF (128*OSTR + CC*WSTR + CC)   /* epilogue max user: 6784 floats; tiles need 4608 */
__global__ void __launch_bounds__(256) flash_kernel(
    const float* __restrict__ ww, const float* __restrict__ wb)
{
    __shared__ float smem_f[SMEMF];

    int b = blockIdx.y, rb = blockIdx.x;
    int tid = threadIdx.x;
    int lane = tid & 31;
    int gi = lane >> 2, tig = lane & 3;
    int warp = tid >> 5;

    const uint32_t* Qw  = g_QH + b*NTOK*16;
    const uint32_t* Kht = g_KHT + (b*64)*16*64;
    const __half*   Vbt = g_VT + b*CIc*NTOK;

    uint32_t* sKH0 = (uint32_t*)smem_f;            // 2 x 16*KHSTR words
    uint32_t* sVW0 = sKH0 + 2*16*KHSTR;            // 2 x 32*VWSTR words

    int r0 = rb*128 + warp*16 + gi;      // rows r0 and r0+8

    // Q fragments: fp16 pairs, log2e-scaled
    uint32_t qf[2][4];
    #pragma unroll
    for (int kt=0; kt<2; kt++){
        qf[kt][0] = Qw[(r0  )*16 + 8*kt + tig    ];
        qf[kt][1] = Qw[(r0+8)*16 + 8*kt + tig    ];
        qf[kt][2] = Qw[(r0  )*16 + 8*kt + tig + 4];
        qf[kt][3] = Qw[(r0+8)*16 + 8*kt + tig + 4];
    }

    float o[4][4];
    #pragma unroll
    for (int nt=0;nt<4;nt++){ o[nt][0]=0.f;o[nt][1]=0.f;o[nt][2]=0.f;o[nt][3]=0.f; }
    float lacc[4] = {0.f, 0.f, 0.f, 0.f};   // ones-column accumulator (rowsum at tig==0)

    // ones-column B-fragment: col 0 of the extra n-group = 1.0 for all 16 k
    uint32_t ones = (gi == 0) ? 0x3C003C00u : 0u;

    // tile-load index patterns (one uint4 per thread for each of K and V)
    int krow = tid >> 4, kwg = tid & 15;   // K: featpair row, word group
    int vd = tid >> 3,   vt = tid & 7;     // V: dim, token-octet

    // ---- prologue: tile 0 into buffer 0 ----
    {
        uint4 kf = *(const uint4*)(Kht + krow*64 + kwg*4);
        uint4 vf = *(const uint4*)(Vbt + vd*NTOK + vt*8);
        *(uint4*)&sKH0[krow*KHSTR + kwg*4] = kf;
        *(uint4*)&sVW0[vd*VWSTR + vt*4] = vf;
    }

    for (int it=0; it<NTOK/64; it++){
        int buf = it & 1;
        uint4 kf, vf;
        if (it < NTOK/64 - 1){
            int tn = it + 1;
            kf = *(const uint4*)(Kht + (tn*16 + krow)*64 + kwg*4);
            vf = *(const uint4*)(Vbt + vd*NTOK + tn*64 + vt*8);
        }
        __syncthreads();

        const uint32_t* kh = sKH0 + buf*(16*KHSTR);
        const uint32_t* vW = sVW0 + buf*(32*VWSTR);

        // ---- S = Q K^T (16 x 64 per warp), fp16 MMA, log2 units ----
        float s[8][4];
        #pragma unroll
        for (int nt=0;nt<8;nt++){ s[nt][0]=0.f;s[nt][1]=0.f;s[nt][2]=0.f;s[nt][3]=0.f; }
        #pragma unroll
        for (int kt=0; kt<2; kt++){
            #pragma unroll
            for (int nt=0; nt<8; nt++){
                uint32_t b0 = kh[(8*kt + tig    )*KHSTR + nt*8 + gi];
                uint32_t b1 = kh[(8*kt + tig + 4)*KHSTR + nt*8 + gi];
                mma_f16(s[nt], qf[kt], b0, b1);
            }
        }

        // ---- softmax numerator in fp16: pack logits, then packed ex2 ----
        uint32_t ph[16];
        #pragma unroll
        for (int kt=0; kt<4; kt++){
            ph[4*kt+0] = pk_f16(s[2*kt  ][0], s[2*kt  ][1]);
            ph[4*kt+1] = pk_f16(s[2*kt  ][2], s[2*kt  ][3]);
            ph[4*kt+2] = pk_f16(s[2*kt+1][0], s[2*kt+1][1]);
            ph[4*kt+3] = pk_f16(s[2*kt+1][2], s[2*kt+1][3]);
        }
        #pragma unroll
        for (int i=0;i<16;i++)
            asm("ex2.approx.f16x2 %0, %0;" : "+r"(ph[i]));

        // ---- O += P V, rowsum += P 1 : fp16 MMA; P words are the A-frags --
        #pragma unroll
        for (int kt=0; kt<4; kt++){
            const uint32_t* a = &ph[4*kt];
            #pragma unroll
            for (int nt=0; nt<4; nt++){
                uint32_t b0 = vW[(nt*8+gi)*VWSTR + kt*8 + tig    ];
                uint32_t b1 = vW[(nt*8+gi)*VWSTR + kt*8 + tig + 4];
                mma_f16(o[nt], a, b0, b1);
            }
            mma_f16(lacc, a, ones, ones);
        }

        // ---- store prefetched tile into the other buffer ----
        if (it < NTOK/64 - 1){
            *(uint4*)&sKH0[(buf^1)*(16*KHSTR) + krow*KHSTR + kwg*4] = kf;
            *(uint4*)&sVW0[(buf^1)*(32*VWSTR) + vd*VWSTR + vt*4] = vf;
        }
    }

    // ---- finalize: row sums live in lacc[0]/lacc[2] of tig==0 lanes ----
    int qbase = lane & ~3;
    float l0 = __shfl_sync(0xffffffffu, lacc[0], qbase);
    float l1 = __shfl_sync(0xffffffffu, lacc[2], qbase);
    float inv0 = 1.f/l0, inv1 = 1.f/l1;

    // ================= fused epilogue: Y = W*O + b, BN partial sums =======
    __syncthreads();   // tiles no longer needed; repurpose smem
    float* sO  = smem_f;                 // [128][OSTR]
    float* sW  = smem_f + 128*OSTR;      // [64][WSTR]
    float* sbb = sW + CC*WSTR;           // [64]

    {   // store normalized O tile (block-local rows)
        int row0 = warp*16 + gi;
        #pragma unroll
        for (int nt=0; nt<4; nt++){
            sO[(row0  )*OSTR + nt*8 + 2*tig    ] = o[nt][0]*inv0;
            sO[(row0  )*OSTR + nt*8 + 2*tig + 1] = o[nt][1]*inv0;
            sO[(row0+8)*OSTR + nt*8 + 2*tig    ] = o[nt][2]*inv1;
            sO[(row0+8)*OSTR + nt*8 + 2*tig + 1] = o[nt][3]*inv1;
        }
    }
    for (int x = tid; x < CC*CIc; x += 256){
        int co = x >> 5, ci = x & 31;
        sW[co*WSTR + ci] = ww[x];
    }
    if (tid < CC) sbb[tid] = wb[tid];
    __syncthreads();

    int co = tid >> 2, grp = tid & 3;
    float wreg[CIc];
    #pragma unroll
    for (int ci=0; ci<CIc; ci++) wreg[ci] = sW[co*WSTR + ci];
    float bias = sbb[co];

    float s1 = 0.f, s2 = 0.f;
    float* yp = g_Y + (b*CC + co)*NTOK + rb*128;
    #pragma unroll 4
    for (int i=0; i<32; i++){
        int n = 4*i + grp;
        const float4* o4 = (const float4*)&sO[n*OSTR];
        float y = bias;
        #pragma unroll
        for (int c4=0; c4<CIc/4; c4++){
            float4 ov = o4[c4];
            y += wreg[4*c4]*ov.x + wreg[4*c4+1]*ov.y
               + wreg[4*c4+2]*ov.z + wreg[4*c4+3]*ov.w;
        }
        yp[n] = y;
        s1 += y; s2 += y*y;
    }
    s1 += __shfl_xor_sync(0xffffffffu, s1, 1);
    s1 += __shfl_xor_sync(0xffffffffu, s1, 2);
    s2 += __shfl_xor_sync(0xffffffffu, s2, 1);
    s2 += __shfl_xor_sync(0xffffffffu, s2, 2);
    if (grp == 0){
        atomicAdd(&g_S1[co], s1);
        atomicAdd(&g_S2[co], s2);
    }
}

// ================= Kernel E: BN affine + bilinear 64->128 + residual ======
// 2 horizontal output pixels per thread (shared y source columns).
__global__ void __launch_bounds__(256) final_kernel(
    const float* __restrict__ gamma, const float* __restrict__ beta,
    const float* __restrict__ mainf, float* __restrict__ out)
{
    int idx2 = blockIdx.x*256 + threadIdx.x;  // [b][co][i 0..127][m 0..63]
    int m  = idx2 & 63;
    int i  = (idx2 >> 6) & 127;
    int co = (idx2 >> 13) & 63;
    int b  = idx2 >> 19;

    float si = 0.5f*i - 0.25f;
    si = fminf(fmaxf(si, 0.f), 63.f);
    int i0 = (int)si; float wi = si - (float)i0; int i1 = min(i0+1, 63);

    int cm1 = max(m-1, 0), cp1 = min(m+1, 63);
    const float* yp  = g_Y + (b*CC + co)*NTOK;
    const float* r0p = yp + (i0 << 6);
    const float* r1p = yp + (i1 << 6);
    float wi0 = 1.f - wi;
    float ya = r0p[cm1]*wi0 + r1p[cm1]*wi;
    float yb = r0p[m  ]*wi0 + r1p[m  ]*wi;
    float yc = r0p[cp1]*wi0 + r1p[cp1]*wi;
    float ve = 0.25f*ya + 0.75f*yb;    // j = 2m   (m==0 clamps: ya==yb)
    float vo = 0.75f*yb + 0.25f*yc;    // j = 2m+1 (m==63 clamps: yc==yb)

    const float invN = 1.f/(BB*NTOK);
    float mean = g_S1[co]*invN;
    float var  = g_S2[co]*invN - mean*mean;
    float rstd = rsqrtf(var + 1e-5f);
    float gsc = rstd*gamma[co];
    float bsc = beta[co] - mean*gsc;

    int base = ((b*CC + co)*HM + i)*HM + 2*m;
    float2 mo = *(const float2*)&mainf[base];
    float2 res;
    res.x = ve*gsc + bsc + mo.x;
    res.y = vo*gsc + bsc + mo.y;
    *(float2*)&out[base] = res;
}

// ======================= launch =======================
extern "C" void kernel_launch(void* const* d_in, const int* in_sizes, int n_in,
                              void* d_out, int out_size)
{
    const float* mainf = (const float*)d_in[0];
    const float* cross = (const float*)d_in[1];
    const float* gw    = (const float*)d_in[2];
    const float* gb    = (const float*)d_in[3];
    const float* tw    = (const float*)d_in[4];
    const float* tb    = (const float*)d_in[5];
    const float* pw    = (const float*)d_in[6];
    const float* pb    = (const float*)d_in[7];
    const float* ww    = (const float*)d_in[8];
    const float* wb    = (const float*)d_in[9];
    const float* gamma = (const float*)d_in[10];
    const float* beta  = (const float*)d_in[11];
    float* out = (float*)d_out;

    qkv_kernel<<<(BB*NTOK)/128, 384>>>(mainf, cross, gw, gb, tw, tb, pw, pb);
    flash_kernel<<<dim3(NTOK/128, BB), 256>>>(ww, wb);
    final_kernel<<<(BB*CC*HM*64)/256, 256>>>(gamma, beta, mainf, out);
}